// round 4
// baseline (speedup 1.0000x reference)
#include <cuda_runtime.h>
#include <cuda_bf16.h>
#include <math_constants.h>
#include <cstdint>
#include <cstddef>

#define BATCH 16
#define TQ 800
#define TK 200

// ---------------------------------------------------------------------------
// Device-global scratch (no allocations allowed)
// ---------------------------------------------------------------------------
__device__ __align__(16) __nv_bfloat16 g_keysbf[BATCH * 512 * TK];
__device__ __align__(16) __nv_bfloat16 g_qbf  [BATCH * 80  * TQ];
__device__ __align__(16) __nv_bfloat16 g_kW1bf[1024 * 1536];
__device__ __align__(16) __nv_bfloat16 g_kW2bf[80 * 1024];
__device__ __align__(16) __nv_bfloat16 g_qW1bf[160 * 240];
__device__ __align__(16) __nv_bfloat16 g_qW2bf[80 * 160];
__device__ __align__(16) __nv_bfloat16 g_qW3bf[80 * 80];
__device__ __align__(16) __nv_bfloat16 g_kh1 [BATCH * 1024 * TK];
__device__ __align__(16) __nv_bfloat16 g_qh1 [BATCH * 160  * TQ];
__device__ __align__(16) __nv_bfloat16 g_qh2 [BATCH * 80   * TQ];
__device__ float g_kenc[BATCH * 80 * TK];
__device__ float g_qenc[BATCH * 80 * TQ];

__device__ __forceinline__ uint32_t smem_to_u32(const void* p) {
    uint32_t a;
    asm("{ .reg .u64 t; cvta.to.shared.u64 t, %1; cvt.u32.u64 %0, t; }" : "=r"(a) : "l"(p));
    return a;
}
__device__ __forceinline__ void ldsm_x4(uint32_t& r0, uint32_t& r1, uint32_t& r2, uint32_t& r3,
                                        uint32_t addr) {
    asm volatile("ldmatrix.sync.aligned.m8n8.x4.shared.b16 {%0,%1,%2,%3}, [%4];"
                 : "=r"(r0), "=r"(r1), "=r"(r2), "=r"(r3) : "r"(addr));
}
__device__ __forceinline__ void mma_bf16(float* c, uint32_t a0, uint32_t a1, uint32_t a2, uint32_t a3,
                                         uint32_t b0, uint32_t b1) {
    asm volatile("mma.sync.aligned.m16n8k16.row.col.f32.bf16.bf16.f32 "
                 "{%0,%1,%2,%3}, {%4,%5,%6,%7}, {%8,%9}, {%0,%1,%2,%3};"
                 : "+f"(c[0]), "+f"(c[1]), "+f"(c[2]), "+f"(c[3])
                 : "r"(a0), "r"(a1), "r"(a2), "r"(a3), "r"(b0), "r"(b1));
}

// ===========================================================================
// Fused f32 -> bf16 conversion of all GEMM operands (one launch).
// ===========================================================================
#define CVT_S0 (BATCH * 512 * TK)     // keys      1,638,400
#define CVT_S1 (BATCH * 80  * TQ)     // queries   1,024,000
#define CVT_S2 (1024 * 1536)          // kW1       1,572,864
#define CVT_S3 (80 * 1024)            // kW2
#define CVT_S4 (160 * 240)            // qW1
#define CVT_S5 (80 * 160)             // qW2
#define CVT_S6 (80 * 80)              // qW3
#define CVT_O1 (CVT_S0)
#define CVT_O2 (CVT_O1 + CVT_S1)
#define CVT_O3 (CVT_O2 + CVT_S2)
#define CVT_O4 (CVT_O3 + CVT_S3)
#define CVT_O5 (CVT_O4 + CVT_S4)
#define CVT_O6 (CVT_O5 + CVT_S5)
#define CVT_TOT (CVT_O6 + CVT_S6)

__global__ __launch_bounds__(256)
void convert_all(const float* __restrict__ keys, const float* __restrict__ queries,
                 const float* __restrict__ kW1, const float* __restrict__ kW2,
                 const float* __restrict__ qW1, const float* __restrict__ qW2,
                 const float* __restrict__ qW3)
{
    const long e = ((long)blockIdx.x * 256 + threadIdx.x) * 4;
    if (e >= CVT_TOT) return;
    const float* src; __nv_bfloat16* dst; long off;
    if      (e < CVT_O1) { src = keys;    dst = g_keysbf; off = e; }
    else if (e < CVT_O2) { src = queries; dst = g_qbf;    off = e - CVT_O1; }
    else if (e < CVT_O3) { src = kW1;     dst = g_kW1bf;  off = e - CVT_O2; }
    else if (e < CVT_O4) { src = kW2;     dst = g_kW2bf;  off = e - CVT_O3; }
    else if (e < CVT_O5) { src = qW1;     dst = g_qW1bf;  off = e - CVT_O4; }
    else if (e < CVT_O6) { src = qW2;     dst = g_qW2bf;  off = e - CVT_O5; }
    else                 { src = qW3;     dst = g_qW3bf;  off = e - CVT_O6; }
    const float4 v = *reinterpret_cast<const float4*>(src + off);
    __nv_bfloat162* d2 = reinterpret_cast<__nv_bfloat162*>(dst + off);
    d2[0] = __float22bfloat162_rn(make_float2(v.x, v.y));
    d2[1] = __float22bfloat162_rn(make_float2(v.z, v.w));
}

// ===========================================================================
// keys conv1 (512 -> 1024, k=3, T=200): mma.sync bf16, CTA tile 128m x 128n.
//   M = 1024 (cout), K = 1536, N = 3200. 8 warps as 4m x 2n; warp 32m x 64n.
// ===========================================================================
#define C1_K  1536
#define C1_LD 72

__global__ __launch_bounds__(256)
void conv1_mma(const __nv_bfloat16* __restrict__ xbf, const __nv_bfloat16* __restrict__ Wbf,
               const float* __restrict__ bias, __nv_bfloat16* __restrict__ y)
{
    __shared__ __align__(16) __nv_bfloat16 As[128 * C1_LD];  // weights (cout rows)
    __shared__ __align__(16) __nv_bfloat16 Bs[128 * C1_LD];  // im2col (n rows)

    const int tid  = threadIdx.x;
    const int wid  = tid >> 5;
    const int lane = tid & 31;
    const int m0 = blockIdx.y * 128;
    const int n0 = blockIdx.x * 128;
    const int warp_m = wid >> 1;   // 0..3
    const int warp_n = wid & 1;    // 0..1

    const uint32_t As_b = smem_to_u32(As);
    const uint32_t Bs_b = smem_to_u32(Bs);
    const uint32_t a_addr0 = As_b + ((warp_m * 32 + (lane & 15)) * C1_LD + (lane >> 4) * 8) * 2;
    const uint32_t b_addr0 = Bs_b + ((warp_n * 64 + (lane & 15)) * C1_LD + (lane >> 4) * 8) * 2;

    float acc[2][8][4];
    #pragma unroll
    for (int mt = 0; mt < 2; mt++)
        #pragma unroll
        for (int nt = 0; nt < 8; nt++)
            #pragma unroll
            for (int i = 0; i < 4; i++) acc[mt][nt][i] = 0.f;

    for (int ch = 0; ch < C1_K / 64; ch++) {
        const int k0 = ch * 64;
        __syncthreads();
        // A: weights, 128 rows x 64 k, uint2 (4 bf16) vectors: 2048 tasks
        #pragma unroll
        for (int j = 0; j < 8; j++) {
            const int e  = j * 256 + tid;
            const int r  = e >> 4;
            const int kq = (e & 15) << 2;
            *reinterpret_cast<uint2*>(&As[r * C1_LD + kq]) =
                *reinterpret_cast<const uint2*>(Wbf + (size_t)(m0 + r) * C1_K + k0 + kq);
        }
        // B: im2col gather, 128 n x 64 k (thread: 4 consecutive n, 1 k -> coalesced)
        #pragma unroll
        for (int j = 0; j < 8; j++) {
            const int rg = tid & 31;
            const int kl = (tid >> 5) + j * 8;
            const int k  = k0 + kl;
            const int ci = k / 3;
            const int w  = k - ci * 3;
            #pragma unroll
            for (int i = 0; i < 4; i++) {
                const int r  = (rg << 2) + i;
                const int n  = n0 + r;
                const int bb = n / TK;
                const int t  = n - bb * TK;
                const int tg = t + w - 1;
                __nv_bfloat16 v = __float2bfloat16(0.f);
                if (tg >= 0 && tg < TK) v = xbf[((size_t)bb * 512 + ci) * TK + tg];
                Bs[r * C1_LD + kl] = v;
            }
        }
        __syncthreads();

        #pragma unroll
        for (int ks = 0; ks < 4; ks++) {
            const uint32_t koff = ks * 32;
            uint32_t a[2][4], b[4][4];
            #pragma unroll
            for (int mt = 0; mt < 2; mt++)
                ldsm_x4(a[mt][0], a[mt][1], a[mt][2], a[mt][3],
                        a_addr0 + mt * 16 * C1_LD * 2 + koff);
            #pragma unroll
            for (int np = 0; np < 4; np++)
                ldsm_x4(b[np][0], b[np][1], b[np][2], b[np][3],
                        b_addr0 + np * 16 * C1_LD * 2 + koff);
            #pragma unroll
            for (int mt = 0; mt < 2; mt++)
                #pragma unroll
                for (int np = 0; np < 4; np++) {
                    mma_bf16(acc[mt][np * 2 + 0], a[mt][0], a[mt][1], a[mt][2], a[mt][3],
                             b[np][0], b[np][2]);
                    mma_bf16(acc[mt][np * 2 + 1], a[mt][0], a[mt][1], a[mt][2], a[mt][3],
                             b[np][1], b[np][3]);
                }
        }
    }

    // Epilogue: bias + relu, bf16 stores
    #pragma unroll
    for (int mt = 0; mt < 2; mt++) {
        const int co = m0 + warp_m * 32 + mt * 16 + (lane >> 2);
        const float bv0 = bias[co];
        const float bv1 = bias[co + 8];
        #pragma unroll
        for (int nt = 0; nt < 8; nt++) {
            const int nb = n0 + warp_n * 64 + nt * 8 + ((lane & 3) << 1);
            #pragma unroll
            for (int cc = 0; cc < 2; cc++) {
                const int n  = nb + cc;
                const int bb = n / TK;
                const int t  = n - bb * TK;
                const size_t base = ((size_t)bb * 1024) * TK + t;
                y[base + (size_t)co * TK]       = __float2bfloat16(fmaxf(acc[mt][nt][cc]     + bv0, 0.f));
                y[base + (size_t)(co + 8) * TK] = __float2bfloat16(fmaxf(acc[mt][nt][2 + cc] + bv1, 0.f));
            }
        }
    }
}

// ===========================================================================
// Generic small conv as mma.sync bf16 with n on the mma M-side.
//   CTA: 128 n-rows x COUT cols (whole COUT per block). 8 warps x 16 n-rows.
// ===========================================================================
template<int CIN, int COUT, int KW, int T, bool RELU, bool OUT_BF16>
__global__ __launch_bounds__(256)
void convN_mma(const __nv_bfloat16* __restrict__ xbf, const __nv_bfloat16* __restrict__ Wbf,
               const float* __restrict__ bias, void* __restrict__ yout)
{
    constexpr int K   = CIN * KW;
    constexpr int KCH = (K + 63) / 64;
    constexpr int PAD = (KW - 1) / 2;
    constexpr int CT  = COUT / 16;

    __shared__ __align__(16) __nv_bfloat16 As[128 * 72];    // im2col (n rows)
    __shared__ __align__(16) __nv_bfloat16 Bs[COUT * 72];   // weights (cout rows)

    const int tid  = threadIdx.x;
    const int wid  = tid >> 5;
    const int lane = tid & 31;
    const int n0   = blockIdx.x * 128;

    const uint32_t As_b = smem_to_u32(As);
    const uint32_t Bs_b = smem_to_u32(Bs);
    const uint32_t a_addr0 = As_b + ((wid * 16 + (lane & 15)) * 72 + (lane >> 4) * 8) * 2;
    const uint32_t b_addr0 = Bs_b + ((lane & 15) * 72 + (lane >> 4) * 8) * 2;

    float acc[CT][2][4];
    #pragma unroll
    for (int ct = 0; ct < CT; ct++)
        #pragma unroll
        for (int s = 0; s < 2; s++)
            #pragma unroll
            for (int i = 0; i < 4; i++) acc[ct][s][i] = 0.f;

    for (int ch = 0; ch < KCH; ch++) {
        const int k0 = ch * 64;
        __syncthreads();
        // A: im2col gather (thread: 4 consecutive n, 1 k)
        #pragma unroll
        for (int j = 0; j < 8; j++) {
            const int rg = tid & 31;
            const int kl = (tid >> 5) + j * 8;
            const int k  = k0 + kl;
            const bool kok = (k < K);
            const int ci = kok ? (k / KW) : 0;
            const int w  = kok ? (k - ci * KW) : 0;
            #pragma unroll
            for (int i = 0; i < 4; i++) {
                const int r  = (rg << 2) + i;
                const int n  = n0 + r;
                const int bb = n / T;
                const int t  = n - bb * T;
                const int tg = t + w - PAD;
                __nv_bfloat16 v = __float2bfloat16(0.f);
                if (kok && tg >= 0 && tg < T) v = xbf[((size_t)bb * CIN + ci) * T + tg];
                As[r * 72 + kl] = v;
            }
        }
        // B: weights, COUT rows x 64 k, uint2 vectors (zero-pad k >= K)
        #pragma unroll
        for (int e = tid; e < COUT * 16; e += 256) {
            const int co = e >> 4;
            const int kq = (e & 15) << 2;
            const int k  = k0 + kq;
            uint2 v = make_uint2(0u, 0u);
            if (k < K) v = *reinterpret_cast<const uint2*>(Wbf + (size_t)co * K + k);
            *reinterpret_cast<uint2*>(&Bs[co * 72 + kq]) = v;
        }
        __syncthreads();

        #pragma unroll
        for (int ks = 0; ks < 4; ks++) {
            const uint32_t koff = ks * 32;
            uint32_t a0, a1, a2, a3;
            ldsm_x4(a0, a1, a2, a3, a_addr0 + koff);
            #pragma unroll
            for (int ct = 0; ct < CT; ct++) {
                uint32_t b0, b1, b2, b3;
                ldsm_x4(b0, b1, b2, b3, b_addr0 + ct * 16 * 72 * 2 + koff);
                mma_bf16(acc[ct][0], a0, a1, a2, a3, b0, b2);
                mma_bf16(acc[ct][1], a0, a1, a2, a3, b1, b3);
            }
        }
    }

    // Epilogue
    #pragma unroll
    for (int ct = 0; ct < CT; ct++)
        #pragma unroll
        for (int s = 0; s < 2; s++)
            #pragma unroll
            for (int i = 0; i < 4; i++) {
                const int co = ct * 16 + s * 8 + ((lane & 3) << 1) + (i & 1);
                const int n  = n0 + wid * 16 + (lane >> 2) + ((i >> 1) << 3);
                const int bb = n / T;
                const int t  = n - bb * T;
                float v = acc[ct][s][i] + bias[co];
                if (RELU) v = fmaxf(v, 0.f);
                const size_t idx = ((size_t)bb * COUT + co) * T + t;
                if (OUT_BF16) reinterpret_cast<__nv_bfloat16*>(yout)[idx] = __float2bfloat16(v);
                else          reinterpret_cast<float*>(yout)[idx] = v;
            }
}

// ---------------------------------------------------------------------------
// Fused attention (unchanged)
// ---------------------------------------------------------------------------
static __device__ __forceinline__ float warp_max(float v) {
    #pragma unroll
    for (int o = 16; o > 0; o >>= 1) v = fmaxf(v, __shfl_xor_sync(0xffffffffu, v, o));
    return v;
}
static __device__ __forceinline__ float warp_sum(float v) {
    #pragma unroll
    for (int o = 16; o > 0; o >>= 1) v += __shfl_xor_sync(0xffffffffu, v, o);
    return v;
}

__global__ __launch_bounds__(256)
void attn_kernel(const float* __restrict__ qenc, const float* __restrict__ kenc,
                 const float* __restrict__ prior, const unsigned char* __restrict__ mask,
                 float* __restrict__ attn_out, float* __restrict__ logp_out)
{
    extern __shared__ float sm[];
    float* Ks  = sm;
    float* Qs  = sm + 80 * TK;
    float* k2s = Qs + 32 * 81;

    const int b   = blockIdx.y;
    const int q0  = blockIdx.x * 32;
    const int tid = threadIdx.x;

    const float* kb = kenc + (size_t)b * 80 * TK;
    for (int i = tid; i < 80 * TK / 4; i += 256)
        reinterpret_cast<float4*>(Ks)[i] = reinterpret_cast<const float4*>(kb)[i];

    const float* qb = qenc + (size_t)b * 80 * TQ;
    {
        const int ql = tid & 31;
        for (int c = tid >> 5; c < 80; c += 8)
            Qs[ql * 81 + c] = qb[c * TQ + q0 + ql];
    }
    __syncthreads();

    for (int k = tid; k < TK; k += 256) {
        float s = 0.f;
        #pragma unroll 8
        for (int c = 0; c < 80; c++) { const float v = Ks[c * TK + k]; s = fmaf(v, v, s); }
        k2s[k] = s;
    }
    __syncthreads();

    const int warp = tid >> 5, lane = tid & 31;
    constexpr int KI = 7;

    float s[4][KI];
    #pragma unroll
    for (int r = 0; r < 4; r++)
        #pragma unroll
        for (int i = 0; i < KI; i++) s[r][i] = 0.f;

    for (int c = 0; c < 80; c++) {
        float qv[4];
        #pragma unroll
        for (int r = 0; r < 4; r++) qv[r] = Qs[(warp * 4 + r) * 81 + c];
        float kv[KI];
        #pragma unroll
        for (int i = 0; i < 6; i++) kv[i] = Ks[c * TK + lane + 32 * i];
        kv[6] = (lane < 8) ? Ks[c * TK + lane + 192] : 0.f;
        #pragma unroll
        for (int r = 0; r < 4; r++)
            #pragma unroll
            for (int i = 0; i < KI; i++)
                s[r][i] = fmaf(qv[r], kv[i], s[r][i]);
    }

    const float NEG_INF = -CUDART_INF_F;
    #pragma unroll
    for (int r = 0; r < 4; r++) {
        const int q = q0 + warp * 4 + r;
        const size_t row = ((size_t)b * TQ + q) * TK;

        float m1 = NEG_INF;
        #pragma unroll
        for (int i = 0; i < KI; i++) {
            const int k = lane + 32 * i;
            const float sc = (k < TK) ? -5e-4f * (k2s[k] - 2.f * s[r][i]) : NEG_INF;
            s[r][i] = sc;
            m1 = fmaxf(m1, sc);
        }
        m1 = warp_max(m1);
        float se = 0.f;
        #pragma unroll
        for (int i = 0; i < KI; i++) {
            const int k = lane + 32 * i;
            if (k < TK) se += __expf(s[r][i] - m1);
        }
        se = warp_sum(se);
        const float lse = m1 + __logf(se);

        float m2 = NEG_INF;
        #pragma unroll
        for (int i = 0; i < KI; i++) {
            const int k = lane + 32 * i;
            if (k < TK) {
                const float lp = s[r][i] - lse + __logf(prior[row + k] + 1e-8f);
                logp_out[row + k] = lp;
                const float t = mask[b * TK + k] ? NEG_INF : lp;
                s[r][i] = t;
                m2 = fmaxf(m2, t);
            }
        }
        m2 = warp_max(m2);
        float se2 = 0.f;
        float e[KI];
        #pragma unroll
        for (int i = 0; i < KI; i++) {
            const int k = lane + 32 * i;
            if (k < TK) { e[i] = __expf(s[r][i] - m2); se2 += e[i]; }
        }
        se2 = warp_sum(se2);
        const float inv = 1.f / se2;
        #pragma unroll
        for (int i = 0; i < KI; i++) {
            const int k = lane + 32 * i;
            if (k < TK) attn_out[row + k] = e[i] * inv;
        }
    }
}

// ---------------------------------------------------------------------------
extern "C" void kernel_launch(void* const* d_in, const int* in_sizes, int n_in,
                              void* d_out, int out_size)
{
    const float* queries = (const float*)d_in[0];
    const float* keys    = (const float*)d_in[1];
    const unsigned char* mask = (const unsigned char*)d_in[3];
    const float* prior   = (const float*)d_in[4];
    const float* kW1 = (const float*)d_in[5];
    const float* kb1 = (const float*)d_in[6];
    const float* kW2 = (const float*)d_in[7];
    const float* kb2 = (const float*)d_in[8];
    const float* qW1 = (const float*)d_in[9];
    const float* qb1 = (const float*)d_in[10];
    const float* qW2 = (const float*)d_in[11];
    const float* qb2 = (const float*)d_in[12];
    const float* qW3 = (const float*)d_in[13];
    const float* qb3 = (const float*)d_in[14];

    float* out      = (float*)d_out;
    float* attn_out = out;
    float* logp_out = out + (size_t)BATCH * TQ * TK;

    __nv_bfloat16 *keysbf, *qbf, *kW1bf, *kW2bf, *qW1bf, *qW2bf, *qW3bf, *kh1, *qh1, *qh2;
    float *kenc, *qenc;
    cudaGetSymbolAddress((void**)&keysbf, g_keysbf);
    cudaGetSymbolAddress((void**)&qbf,    g_qbf);
    cudaGetSymbolAddress((void**)&kW1bf,  g_kW1bf);
    cudaGetSymbolAddress((void**)&kW2bf,  g_kW2bf);
    cudaGetSymbolAddress((void**)&qW1bf,  g_qW1bf);
    cudaGetSymbolAddress((void**)&qW2bf,  g_qW2bf);
    cudaGetSymbolAddress((void**)&qW3bf,  g_qW3bf);
    cudaGetSymbolAddress((void**)&kh1,    g_kh1);
    cudaGetSymbolAddress((void**)&qh1,    g_qh1);
    cudaGetSymbolAddress((void**)&qh2,    g_qh2);
    cudaGetSymbolAddress((void**)&kenc,   g_kenc);
    cudaGetSymbolAddress((void**)&qenc,   g_qenc);

    // 0) f32 -> bf16 operand conversion (single launch)
    convert_all<<<(CVT_TOT / 4 + 255) / 256, 256>>>(keys, queries, kW1, kW2, qW1, qW2, qW3);

    // 1) keys conv1 (512->1024, k3) tensor-core
    conv1_mma<<<dim3(BATCH * TK / 128, 1024 / 128), 256>>>(keysbf, kW1bf, kb1, kh1);

    // 2) keys conv2 (1024->80, pw) tensor-core
    convN_mma<1024, 80, 1, TK, false, false><<<BATCH * TK / 128, 256>>>(kh1, kW2bf, kb2, kenc);

    // 3) queries path, all tensor-core
    convN_mma<80, 160, 3, TQ, true,  true ><<<BATCH * TQ / 128, 256>>>(qbf, qW1bf, qb1, qh1);
    convN_mma<160, 80, 1, TQ, true,  true ><<<BATCH * TQ / 128, 256>>>(qh1, qW2bf, qb2, qh2);
    convN_mma<80,  80, 1, TQ, false, false><<<BATCH * TQ / 128, 256>>>(qh2, qW3bf, qb3, qenc);

    // 4) fused attention
    const int smem = (80 * TK + 32 * 81 + TK) * (int)sizeof(float);
    cudaFuncSetAttribute(attn_kernel, cudaFuncAttributeMaxDynamicSharedMemorySize, smem);
    attn_kernel<<<dim3(TQ / 32, BATCH), 256, smem>>>(qenc, kenc, prior, mask, attn_out, logp_out);
}

// round 5
// speedup vs baseline: 1.4876x; 1.4876x over previous
#include <cuda_runtime.h>
#include <cuda_bf16.h>
#include <math_constants.h>
#include <cstdint>
#include <cstddef>

#define BATCH 16
#define TQ 800
#define TK 200

// ---------------------------------------------------------------------------
// Device-global scratch (no allocations allowed)
// ---------------------------------------------------------------------------
__device__ __align__(16) __nv_bfloat16 g_keysbf[BATCH * 512 * TK];
__device__ __align__(16) __nv_bfloat16 g_qbf  [BATCH * 80  * TQ];
__device__ __align__(16) __nv_bfloat16 g_kW1bf[1024 * 1536];
__device__ __align__(16) __nv_bfloat16 g_kW2bf[80 * 1024];
__device__ __align__(16) __nv_bfloat16 g_qW1bf[160 * 240];
__device__ __align__(16) __nv_bfloat16 g_qW2bf[80 * 160];
__device__ __align__(16) __nv_bfloat16 g_qW3bf[80 * 80];
__device__ float g_kenc[BATCH * 80 * TK];
__device__ float g_qenc[BATCH * 80 * TQ];

__device__ __forceinline__ uint32_t smem_to_u32(const void* p) {
    uint32_t a;
    asm("{ .reg .u64 t; cvta.to.shared.u64 t, %1; cvt.u32.u64 %0, t; }" : "=r"(a) : "l"(p));
    return a;
}
__device__ __forceinline__ void ldsm_x4(uint32_t& r0, uint32_t& r1, uint32_t& r2, uint32_t& r3,
                                        uint32_t addr) {
    asm volatile("ldmatrix.sync.aligned.m8n8.x4.shared.b16 {%0,%1,%2,%3}, [%4];"
                 : "=r"(r0), "=r"(r1), "=r"(r2), "=r"(r3) : "r"(addr));
}
__device__ __forceinline__ void mma_bf16(float* c, uint32_t a0, uint32_t a1, uint32_t a2, uint32_t a3,
                                         uint32_t b0, uint32_t b1) {
    asm volatile("mma.sync.aligned.m16n8k16.row.col.f32.bf16.bf16.f32 "
                 "{%0,%1,%2,%3}, {%4,%5,%6,%7}, {%8,%9}, {%0,%1,%2,%3};"
                 : "+f"(c[0]), "+f"(c[1]), "+f"(c[2]), "+f"(c[3])
                 : "r"(a0), "r"(a1), "r"(a2), "r"(a3), "r"(b0), "r"(b1));
}

// ===========================================================================
// Fused f32 -> bf16 conversion of all GEMM operands (one launch).
// ===========================================================================
#define CVT_S0 (BATCH * 512 * TK)
#define CVT_S1 (BATCH * 80  * TQ)
#define CVT_S2 (1024 * 1536)
#define CVT_S3 (80 * 1024)
#define CVT_S4 (160 * 240)
#define CVT_S5 (80 * 160)
#define CVT_S6 (80 * 80)
#define CVT_O1 (CVT_S0)
#define CVT_O2 (CVT_O1 + CVT_S1)
#define CVT_O3 (CVT_O2 + CVT_S2)
#define CVT_O4 (CVT_O3 + CVT_S3)
#define CVT_O5 (CVT_O4 + CVT_S4)
#define CVT_O6 (CVT_O5 + CVT_S5)
#define CVT_TOT (CVT_O6 + CVT_S6)

__global__ __launch_bounds__(256)
void convert_all(const float* __restrict__ keys, const float* __restrict__ queries,
                 const float* __restrict__ kW1, const float* __restrict__ kW2,
                 const float* __restrict__ qW1, const float* __restrict__ qW2,
                 const float* __restrict__ qW3)
{
    const long e = ((long)blockIdx.x * 256 + threadIdx.x) * 4;
    if (e >= CVT_TOT) return;
    const float* src; __nv_bfloat16* dst; long off;
    if      (e < CVT_O1) { src = keys;    dst = g_keysbf; off = e; }
    else if (e < CVT_O2) { src = queries; dst = g_qbf;    off = e - CVT_O1; }
    else if (e < CVT_O3) { src = kW1;     dst = g_kW1bf;  off = e - CVT_O2; }
    else if (e < CVT_O4) { src = kW2;     dst = g_kW2bf;  off = e - CVT_O3; }
    else if (e < CVT_O5) { src = qW1;     dst = g_qW1bf;  off = e - CVT_O4; }
    else if (e < CVT_O6) { src = qW2;     dst = g_qW2bf;  off = e - CVT_O5; }
    else                 { src = qW3;     dst = g_qW3bf;  off = e - CVT_O6; }
    const float4 v = *reinterpret_cast<const float4*>(src + off);
    __nv_bfloat162* d2 = reinterpret_cast<__nv_bfloat162*>(dst + off);
    d2[0] = __float22bfloat162_rn(make_float2(v.x, v.y));
    d2[1] = __float22bfloat162_rn(make_float2(v.z, v.w));
}

// Initialize kenc[b][co][t] = kb2[co]  (conv1 kernel atomicAdds partials onto it)
__global__ __launch_bounds__(256)
void init_kenc(const float* __restrict__ kb2)
{
    const int idx = blockIdx.x * 256 + threadIdx.x;
    if (idx < BATCH * 80 * TK)
        g_kenc[idx] = kb2[(idx / TK) % 80];
}

// ===========================================================================
// keys conv1 (512->1024, k3) + FUSED pointwise conv2 (1024->80) via split-K.
//   GEMM1: M=1024(cout) K=1536 N=3200, CTA tile 128m x 128n.
//   Then per-CTA: partial2[80, 128n] = W2[80, m-slice] @ relu(tile) -> atomicAdd.
// ===========================================================================
#define C1_K   1536
#define C1_LD  72
#define C2_LD  136
// dynamic smem: phase1 As[128*72]+Bs[128*72]=36864; phase2 Sh[128*136]=34816 @0, W2s[80*136]=21760 @34816
#define C1_SMEM 56576

__global__ __launch_bounds__(256)
void conv1_fused(const __nv_bfloat16* __restrict__ xbf, const __nv_bfloat16* __restrict__ W1,
                 const float* __restrict__ bias1, const __nv_bfloat16* __restrict__ W2,
                 float* __restrict__ kenc)
{
    extern __shared__ char dsm[];
    __nv_bfloat16* As  = reinterpret_cast<__nv_bfloat16*>(dsm);           // 128 cout x 72
    __nv_bfloat16* Bs  = reinterpret_cast<__nv_bfloat16*>(dsm + 18432);   // 128 n x 72
    __nv_bfloat16* Sh  = reinterpret_cast<__nv_bfloat16*>(dsm);           // 128 n x 136 (phase2)
    __nv_bfloat16* W2s = reinterpret_cast<__nv_bfloat16*>(dsm + 34816);   // 80 x 136 (phase2)

    const int tid  = threadIdx.x;
    const int wid  = tid >> 5;
    const int lane = tid & 31;
    const int m0 = blockIdx.y * 128;
    const int n0 = blockIdx.x * 128;
    const int warp_m = wid >> 1;
    const int warp_n = wid & 1;

    const uint32_t As_b = smem_to_u32(As);
    const uint32_t Bs_b = smem_to_u32(Bs);
    const uint32_t a_addr0 = As_b + ((warp_m * 32 + (lane & 15)) * C1_LD + (lane >> 4) * 8) * 2;
    const uint32_t b_addr0 = Bs_b + ((warp_n * 64 + (lane & 15)) * C1_LD + (lane >> 4) * 8) * 2;

    float acc[2][8][4];
    #pragma unroll
    for (int mt = 0; mt < 2; mt++)
        #pragma unroll
        for (int nt = 0; nt < 8; nt++)
            #pragma unroll
            for (int i = 0; i < 4; i++) acc[mt][nt][i] = 0.f;

    for (int ch = 0; ch < C1_K / 64; ch++) {
        const int k0 = ch * 64;
        __syncthreads();
        #pragma unroll
        for (int j = 0; j < 8; j++) {
            const int e  = j * 256 + tid;
            const int r  = e >> 4;
            const int kq = (e & 15) << 2;
            *reinterpret_cast<uint2*>(&As[r * C1_LD + kq]) =
                *reinterpret_cast<const uint2*>(W1 + (size_t)(m0 + r) * C1_K + k0 + kq);
        }
        #pragma unroll
        for (int j = 0; j < 8; j++) {
            const int rg = tid & 31;
            const int kl = (tid >> 5) + j * 8;
            const int k  = k0 + kl;
            const int ci = k / 3;
            const int w  = k - ci * 3;
            #pragma unroll
            for (int i = 0; i < 4; i++) {
                const int r  = (rg << 2) + i;
                const int n  = n0 + r;
                const int bb = n / TK;
                const int t  = n - bb * TK;
                const int tg = t + w - 1;
                __nv_bfloat16 v = __float2bfloat16(0.f);
                if (tg >= 0 && tg < TK) v = xbf[((size_t)bb * 512 + ci) * TK + tg];
                Bs[r * C1_LD + kl] = v;
            }
        }
        __syncthreads();

        #pragma unroll
        for (int ks = 0; ks < 4; ks++) {
            const uint32_t koff = ks * 32;
            uint32_t a[2][4], b[4][4];
            #pragma unroll
            for (int mt = 0; mt < 2; mt++)
                ldsm_x4(a[mt][0], a[mt][1], a[mt][2], a[mt][3],
                        a_addr0 + mt * 16 * C1_LD * 2 + koff);
            #pragma unroll
            for (int np = 0; np < 4; np++)
                ldsm_x4(b[np][0], b[np][1], b[np][2], b[np][3],
                        b_addr0 + np * 16 * C1_LD * 2 + koff);
            #pragma unroll
            for (int mt = 0; mt < 2; mt++)
                #pragma unroll
                for (int np = 0; np < 4; np++) {
                    mma_bf16(acc[mt][np * 2 + 0], a[mt][0], a[mt][1], a[mt][2], a[mt][3],
                             b[np][0], b[np][2]);
                    mma_bf16(acc[mt][np * 2 + 1], a[mt][0], a[mt][1], a[mt][2], a[mt][3],
                             b[np][1], b[np][3]);
                }
        }
    }
    __syncthreads();   // all warps done reading As/Bs

    // Phase 2a: stage relu(tile) transposed -> Sh[n_local][cout_local] (bf16)
    #pragma unroll
    for (int mt = 0; mt < 2; mt++) {
        const int col = warp_m * 32 + mt * 16 + (lane >> 2);
        const float bv0 = bias1[m0 + col];
        const float bv1 = bias1[m0 + col + 8];
        #pragma unroll
        for (int nt = 0; nt < 8; nt++) {
            const int nb = warp_n * 64 + nt * 8 + ((lane & 3) << 1);
            #pragma unroll
            for (int cc = 0; cc < 2; cc++) {
                Sh[(nb + cc) * C2_LD + col]     = __float2bfloat16(fmaxf(acc[mt][nt][cc]     + bv0, 0.f));
                Sh[(nb + cc) * C2_LD + col + 8] = __float2bfloat16(fmaxf(acc[mt][nt][2 + cc] + bv1, 0.f));
            }
        }
    }
    // Phase 2b: load W2 slice [80 x 128] (cols m0..m0+127)
    for (int e = tid; e < 80 * 32; e += 256) {
        const int r = e >> 5;
        const int q = (e & 31) << 2;
        *reinterpret_cast<uint2*>(&W2s[r * C2_LD + q]) =
            *reinterpret_cast<const uint2*>(W2 + (size_t)r * 1024 + m0 + q);
    }
    __syncthreads();

    // Phase 2c: partial [128n x 80co2] over k=128 local couts; 8 warps x 16 rows
    const uint32_t sh_addr = smem_to_u32(Sh)  + ((wid * 16 + (lane & 15)) * C2_LD + (lane >> 4) * 8) * 2;
    const uint32_t w2_addr = smem_to_u32(W2s) + ((lane & 15) * C2_LD + (lane >> 4) * 8) * 2;
    float acc2[5][2][4];
    #pragma unroll
    for (int ct = 0; ct < 5; ct++)
        #pragma unroll
        for (int s = 0; s < 2; s++)
            #pragma unroll
            for (int i = 0; i < 4; i++) acc2[ct][s][i] = 0.f;

    #pragma unroll
    for (int ks = 0; ks < 8; ks++) {
        const uint32_t koff = ks * 32;
        uint32_t a0, a1, a2, a3;
        ldsm_x4(a0, a1, a2, a3, sh_addr + koff);
        #pragma unroll
        for (int ct = 0; ct < 5; ct++) {
            uint32_t b0, b1, b2, b3;
            ldsm_x4(b0, b1, b2, b3, w2_addr + ct * 16 * C2_LD * 2 + koff);
            mma_bf16(acc2[ct][0], a0, a1, a2, a3, b0, b2);
            mma_bf16(acc2[ct][1], a0, a1, a2, a3, b1, b3);
        }
    }
    // Phase 2d: atomic accumulate into kenc (f32)
    #pragma unroll
    for (int ct = 0; ct < 5; ct++)
        #pragma unroll
        for (int s = 0; s < 2; s++)
            #pragma unroll
            for (int i = 0; i < 4; i++) {
                const int co2 = ct * 16 + s * 8 + ((lane & 3) << 1) + (i & 1);
                const int n   = n0 + wid * 16 + (lane >> 2) + ((i >> 1) << 3);
                const int bb  = n / TK;
                const int t   = n - bb * TK;
                atomicAdd(kenc + ((size_t)bb * 80 + co2) * TK + t, acc2[ct][s][i]);
            }
}

// ===========================================================================
// FUSED query path: conv(80->160,k3)+relu -> conv(160->80)+relu -> conv(80->80)
// One CTA per 128-n tile; intermediates in smem.
// ===========================================================================
#define QF_SMEM 185856

__global__ __launch_bounds__(256)
void fused_q(const __nv_bfloat16* __restrict__ qbf,
             const __nv_bfloat16* __restrict__ W1, const float* __restrict__ b1,
             const __nv_bfloat16* __restrict__ W2, const float* __restrict__ b2,
             const __nv_bfloat16* __restrict__ W3, const float* __restrict__ b3,
             float* __restrict__ qenc)
{
    extern __shared__ char dsm[];
    __nv_bfloat16* A1  = reinterpret_cast<__nv_bfloat16*>(dsm);            // 128 x 248
    __nv_bfloat16* W1s = reinterpret_cast<__nv_bfloat16*>(dsm + 63488);    // 160 x 248
    __nv_bfloat16* H1  = reinterpret_cast<__nv_bfloat16*>(dsm + 142848);   // 128 x 168
    __nv_bfloat16* W2s = reinterpret_cast<__nv_bfloat16*>(dsm);            // 80 x 168 (over A1)
    __nv_bfloat16* H2  = reinterpret_cast<__nv_bfloat16*>(dsm + 26880);    // 128 x 88 (over A1)
    __nv_bfloat16* W3s = reinterpret_cast<__nv_bfloat16*>(dsm + 49408);    // 80 x 88  (over A1)

    const int tid  = threadIdx.x;
    const int wid  = tid >> 5;
    const int lane = tid & 31;
    const int n0   = blockIdx.x * 128;
    const int rowq = (lane & 15);
    const int kq8  = (lane >> 4) * 8;

    // --- fill A1: im2col(queries) 128 n x 240 k ---
    #pragma unroll
    for (int j = 0; j < 30; j++) {
        const int kl = (tid >> 5) + j * 8;     // 0..239
        const int ci = kl / 3;
        const int w  = kl - ci * 3;
        #pragma unroll
        for (int i = 0; i < 4; i++) {
            const int r  = ((tid & 31) << 2) + i;
            const int n  = n0 + r;
            const int bb = n / TQ;
            const int t  = n - bb * TQ;
            const int tg = t + w - 1;
            __nv_bfloat16 v = __float2bfloat16(0.f);
            if (tg >= 0 && tg < TQ) v = qbf[((size_t)bb * 80 + ci) * TQ + tg];
            A1[r * 248 + kl] = v;
        }
    }
    // --- fill W1s: 160 x 240 ---
    for (int e = tid; e < 160 * 60; e += 256) {
        const int r = e / 60;
        const int q = (e - r * 60) * 4;
        *reinterpret_cast<uint2*>(&W1s[r * 248 + q]) =
            *reinterpret_cast<const uint2*>(W1 + (size_t)r * 240 + q);
    }
    __syncthreads();

    // --- stage 1: [128n x 160co], K=240 (15 ks), CT=10 ---
    {
        const uint32_t a_addr = smem_to_u32(A1)  + ((wid * 16 + rowq) * 248 + kq8) * 2;
        const uint32_t b_addr = smem_to_u32(W1s) + (rowq * 248 + kq8) * 2;
        float acc1[10][2][4];
        #pragma unroll
        for (int ct = 0; ct < 10; ct++)
            #pragma unroll
            for (int s = 0; s < 2; s++)
                #pragma unroll
                for (int i = 0; i < 4; i++) acc1[ct][s][i] = 0.f;
        #pragma unroll
        for (int ks = 0; ks < 15; ks++) {
            const uint32_t koff = ks * 32;
            uint32_t a0, a1, a2, a3;
            ldsm_x4(a0, a1, a2, a3, a_addr + koff);
            #pragma unroll
            for (int ct = 0; ct < 10; ct++) {
                uint32_t b0, b1, b2, b3;
                ldsm_x4(b0, b1, b2, b3, b_addr + ct * 16 * 248 * 2 + koff);
                mma_bf16(acc1[ct][0], a0, a1, a2, a3, b0, b2);
                mma_bf16(acc1[ct][1], a0, a1, a2, a3, b1, b3);
            }
        }
        __syncthreads();   // done reading A1/W1s
        // H1[n][co] = relu(acc + b1)
        #pragma unroll
        for (int ct = 0; ct < 10; ct++)
            #pragma unroll
            for (int s = 0; s < 2; s++)
                #pragma unroll
                for (int i = 0; i < 4; i++) {
                    const int co = ct * 16 + s * 8 + ((lane & 3) << 1) + (i & 1);
                    const int nl = wid * 16 + (lane >> 2) + ((i >> 1) << 3);
                    H1[nl * 168 + co] = __float2bfloat16(fmaxf(acc1[ct][s][i] + b1[co], 0.f));
                }
    }
    // --- fill W2s: 80 x 160 ---
    for (int e = tid; e < 80 * 40; e += 256) {
        const int r = e / 40;
        const int q = (e - r * 40) * 4;
        *reinterpret_cast<uint2*>(&W2s[r * 168 + q]) =
            *reinterpret_cast<const uint2*>(W2 + (size_t)r * 160 + q);
    }
    __syncthreads();

    // --- stage 2: [128n x 80co], K=160 (10 ks), CT=5 ---
    {
        const uint32_t a_addr = smem_to_u32(H1)  + ((wid * 16 + rowq) * 168 + kq8) * 2;
        const uint32_t b_addr = smem_to_u32(W2s) + (rowq * 168 + kq8) * 2;
        float acc2[5][2][4];
        #pragma unroll
        for (int ct = 0; ct < 5; ct++)
            #pragma unroll
            for (int s = 0; s < 2; s++)
                #pragma unroll
                for (int i = 0; i < 4; i++) acc2[ct][s][i] = 0.f;
        #pragma unroll
        for (int ks = 0; ks < 10; ks++) {
            const uint32_t koff = ks * 32;
            uint32_t a0, a1, a2, a3;
            ldsm_x4(a0, a1, a2, a3, a_addr + koff);
            #pragma unroll
            for (int ct = 0; ct < 5; ct++) {
                uint32_t b0, b1, b2, b3;
                ldsm_x4(b0, b1, b2, b3, b_addr + ct * 16 * 168 * 2 + koff);
                mma_bf16(acc2[ct][0], a0, a1, a2, a3, b0, b2);
                mma_bf16(acc2[ct][1], a0, a1, a2, a3, b1, b3);
            }
        }
        __syncthreads();
        #pragma unroll
        for (int ct = 0; ct < 5; ct++)
            #pragma unroll
            for (int s = 0; s < 2; s++)
                #pragma unroll
                for (int i = 0; i < 4; i++) {
                    const int co = ct * 16 + s * 8 + ((lane & 3) << 1) + (i & 1);
                    const int nl = wid * 16 + (lane >> 2) + ((i >> 1) << 3);
                    H2[nl * 88 + co] = __float2bfloat16(fmaxf(acc2[ct][s][i] + b2[co], 0.f));
                }
    }
    // --- fill W3s: 80 x 80 ---
    for (int e = tid; e < 80 * 20; e += 256) {
        const int r = e / 20;
        const int q = (e - r * 20) * 4;
        *reinterpret_cast<uint2*>(&W3s[r * 88 + q]) =
            *reinterpret_cast<const uint2*>(W3 + (size_t)r * 80 + q);
    }
    __syncthreads();

    // --- stage 3: [128n x 80co], K=80 (5 ks), CT=5 -> qenc (f32) ---
    {
        const uint32_t a_addr = smem_to_u32(H2)  + ((wid * 16 + rowq) * 88 + kq8) * 2;
        const uint32_t b_addr = smem_to_u32(W3s) + (rowq * 88 + kq8) * 2;
        float acc3[5][2][4];
        #pragma unroll
        for (int ct = 0; ct < 5; ct++)
            #pragma unroll
            for (int s = 0; s < 2; s++)
                #pragma unroll
                for (int i = 0; i < 4; i++) acc3[ct][s][i] = 0.f;
        #pragma unroll
        for (int ks = 0; ks < 5; ks++) {
            const uint32_t koff = ks * 32;
            uint32_t a0, a1, a2, a3;
            ldsm_x4(a0, a1, a2, a3, a_addr + koff);
            #pragma unroll
            for (int ct = 0; ct < 5; ct++) {
                uint32_t b0, b1, b2, b3;
                ldsm_x4(b0, b1, b2, b3, b_addr + ct * 16 * 88 * 2 + koff);
                mma_bf16(acc3[ct][0], a0, a1, a2, a3, b0, b2);
                mma_bf16(acc3[ct][1], a0, a1, a2, a3, b1, b3);
            }
        }
        #pragma unroll
        for (int ct = 0; ct < 5; ct++)
            #pragma unroll
            for (int s = 0; s < 2; s++)
                #pragma unroll
                for (int i = 0; i < 4; i++) {
                    const int co = ct * 16 + s * 8 + ((lane & 3) << 1) + (i & 1);
                    const int n  = n0 + wid * 16 + (lane >> 2) + ((i >> 1) << 3);
                    const int bb = n / TQ;
                    const int t  = n - bb * TQ;
                    qenc[((size_t)bb * 80 + co) * TQ + t] = acc3[ct][s][i] + b3[co];
                }
    }
}

// ---------------------------------------------------------------------------
// Fused attention. softmax(logsoftmax(s)+log(p)) == normalize(exp(s-m1)*p):
// second max/exp pass eliminated.
// ---------------------------------------------------------------------------
static __device__ __forceinline__ float warp_max(float v) {
    #pragma unroll
    for (int o = 16; o > 0; o >>= 1) v = fmaxf(v, __shfl_xor_sync(0xffffffffu, v, o));
    return v;
}
static __device__ __forceinline__ float warp_sum(float v) {
    #pragma unroll
    for (int o = 16; o > 0; o >>= 1) v += __shfl_xor_sync(0xffffffffu, v, o);
    return v;
}

__global__ __launch_bounds__(256)
void attn_kernel(const float* __restrict__ qenc, const float* __restrict__ kenc,
                 const float* __restrict__ prior, const unsigned char* __restrict__ mask,
                 float* __restrict__ attn_out, float* __restrict__ logp_out)
{
    extern __shared__ float sm[];
    float* Ks  = sm;
    float* Qs  = sm + 80 * TK;
    float* k2s = Qs + 32 * 81;

    const int b   = blockIdx.y;
    const int q0  = blockIdx.x * 32;
    const int tid = threadIdx.x;

    const float* kb = kenc + (size_t)b * 80 * TK;
    for (int i = tid; i < 80 * TK / 4; i += 256)
        reinterpret_cast<float4*>(Ks)[i] = reinterpret_cast<const float4*>(kb)[i];

    const float* qb = qenc + (size_t)b * 80 * TQ;
    {
        const int ql = tid & 31;
        for (int c = tid >> 5; c < 80; c += 8)
            Qs[ql * 81 + c] = qb[c * TQ + q0 + ql];
    }
    __syncthreads();

    for (int k = tid; k < TK; k += 256) {
        float s = 0.f;
        #pragma unroll 8
        for (int c = 0; c < 80; c++) { const float v = Ks[c * TK + k]; s = fmaf(v, v, s); }
        k2s[k] = s;
    }
    __syncthreads();

    const int warp = tid >> 5, lane = tid & 31;
    constexpr int KI = 7;

    float s[4][KI];
    #pragma unroll
    for (int r = 0; r < 4; r++)
        #pragma unroll
        for (int i = 0; i < KI; i++) s[r][i] = 0.f;

    for (int c = 0; c < 80; c++) {
        float qv[4];
        #pragma unroll
        for (int r = 0; r < 4; r++) qv[r] = Qs[(warp * 4 + r) * 81 + c];
        float kv[KI];
        #pragma unroll
        for (int i = 0; i < 6; i++) kv[i] = Ks[c * TK + lane + 32 * i];
        kv[6] = (lane < 8) ? Ks[c * TK + lane + 192] : 0.f;
        #pragma unroll
        for (int r = 0; r < 4; r++)
            #pragma unroll
            for (int i = 0; i < KI; i++)
                s[r][i] = fmaf(qv[r], kv[i], s[r][i]);
    }

    const float NEG_INF = -CUDART_INF_F;
    #pragma unroll
    for (int r = 0; r < 4; r++) {
        const int q = q0 + warp * 4 + r;
        const size_t row = ((size_t)b * TQ + q) * TK;

        float m1 = NEG_INF;
        #pragma unroll
        for (int i = 0; i < KI; i++) {
            const int k = lane + 32 * i;
            const float sc = (k < TK) ? -5e-4f * (k2s[k] - 2.f * s[r][i]) : NEG_INF;
            s[r][i] = sc;
            m1 = fmaxf(m1, sc);
        }
        m1 = warp_max(m1);

        float e[KI];
        float se = 0.f;
        #pragma unroll
        for (int i = 0; i < KI; i++) {
            const int k = lane + 32 * i;
            if (k < TK) { e[i] = __expf(s[r][i] - m1); se += e[i]; }
        }
        se = warp_sum(se);
        const float lse = m1 + __logf(se);

        float se2 = 0.f;
        #pragma unroll
        for (int i = 0; i < KI; i++) {
            const int k = lane + 32 * i;
            if (k < TK) {
                const float pr = prior[row + k] + 1e-8f;
                logp_out[row + k] = s[r][i] - lse + __logf(pr);
                const float wv = mask[b * TK + k] ? 0.f : e[i] * pr;
                e[i] = wv;
                se2 += wv;
            }
        }
        se2 = warp_sum(se2);
        const float inv = 1.f / se2;
        #pragma unroll
        for (int i = 0; i < KI; i++) {
            const int k = lane + 32 * i;
            if (k < TK) attn_out[row + k] = e[i] * inv;
        }
    }
}

// ---------------------------------------------------------------------------
extern "C" void kernel_launch(void* const* d_in, const int* in_sizes, int n_in,
                              void* d_out, int out_size)
{
    const float* queries = (const float*)d_in[0];
    const float* keys    = (const float*)d_in[1];
    const unsigned char* mask = (const unsigned char*)d_in[3];
    const float* prior   = (const float*)d_in[4];
    const float* kW1 = (const float*)d_in[5];
    const float* kb1 = (const float*)d_in[6];
    const float* kW2 = (const float*)d_in[7];
    const float* kb2 = (const float*)d_in[8];
    const float* qW1 = (const float*)d_in[9];
    const float* qb1 = (const float*)d_in[10];
    const float* qW2 = (const float*)d_in[11];
    const float* qb2 = (const float*)d_in[12];
    const float* qW3 = (const float*)d_in[13];
    const float* qb3 = (const float*)d_in[14];

    float* out      = (float*)d_out;
    float* attn_out = out;
    float* logp_out = out + (size_t)BATCH * TQ * TK;

    __nv_bfloat16 *keysbf, *qbf, *kW1bf, *kW2bf, *qW1bf, *qW2bf, *qW3bf;
    float *kenc, *qenc;
    cudaGetSymbolAddress((void**)&keysbf, g_keysbf);
    cudaGetSymbolAddress((void**)&qbf,    g_qbf);
    cudaGetSymbolAddress((void**)&kW1bf,  g_kW1bf);
    cudaGetSymbolAddress((void**)&kW2bf,  g_kW2bf);
    cudaGetSymbolAddress((void**)&qW1bf,  g_qW1bf);
    cudaGetSymbolAddress((void**)&qW2bf,  g_qW2bf);
    cudaGetSymbolAddress((void**)&qW3bf,  g_qW3bf);
    cudaGetSymbolAddress((void**)&kenc,   g_kenc);
    cudaGetSymbolAddress((void**)&qenc,   g_qenc);

    // 0) f32 -> bf16 operands + kenc = bias init
    convert_all<<<(CVT_TOT / 4 + 255) / 256, 256>>>(keys, queries, kW1, kW2, qW1, qW2, qW3);
    init_kenc<<<(BATCH * 80 * TK + 255) / 256, 256>>>(kb2);

    // 1) keys conv1 + fused pointwise conv2 (split-K atomics into kenc)
    cudaFuncSetAttribute(conv1_fused, cudaFuncAttributeMaxDynamicSharedMemorySize, C1_SMEM);
    conv1_fused<<<dim3(BATCH * TK / 128, 1024 / 128), 256, C1_SMEM>>>(keysbf, kW1bf, kb1, kW2bf, kenc);

    // 2) fused query path (3 convs in one kernel)
    cudaFuncSetAttribute(fused_q, cudaFuncAttributeMaxDynamicSharedMemorySize, QF_SMEM);
    fused_q<<<BATCH * TQ / 128, 256, QF_SMEM>>>(qbf, qW1bf, qb1, qW2bf, qb2, qW3bf, qb3, qenc);

    // 3) fused attention
    const int smem = (80 * TK + 32 * 81 + TK) * (int)sizeof(float);
    cudaFuncSetAttribute(attn_kernel, cudaFuncAttributeMaxDynamicSharedMemorySize, smem);
    attn_kernel<<<dim3(TQ / 32, BATCH), 256, smem>>>(qenc, kenc, prior, mask, attn_out, logp_out);
}

// round 6
// speedup vs baseline: 2.7366x; 1.8396x over previous
#include <cuda_runtime.h>
#include <cuda_bf16.h>
#include <math_constants.h>
#include <cstdint>
#include <cstddef>

#define BATCH 16
#define TQ 800
#define TK 200

// ---------------------------------------------------------------------------
// Device-global scratch (no allocations allowed)
// ---------------------------------------------------------------------------
__device__ __align__(16) __nv_bfloat16 g_kcol [BATCH * TK * 1536];   // im2col(keys)
__device__ __align__(16) __nv_bfloat16 g_qbf  [BATCH * 80  * TQ];
__device__ __align__(16) __nv_bfloat16 g_kW1bf[1024 * 1536];
__device__ __align__(16) __nv_bfloat16 g_kW2bf[80 * 1024];
__device__ __align__(16) __nv_bfloat16 g_qW1bf[160 * 240];
__device__ __align__(16) __nv_bfloat16 g_qW2bf[80 * 160];
__device__ __align__(16) __nv_bfloat16 g_qW3bf[80 * 80];
__device__ float g_kenc[BATCH * 80 * TK];
__device__ float g_qenc[BATCH * 80 * TQ];

__device__ __forceinline__ uint32_t smem_to_u32(const void* p) {
    uint32_t a;
    asm("{ .reg .u64 t; cvta.to.shared.u64 t, %1; cvt.u32.u64 %0, t; }" : "=r"(a) : "l"(p));
    return a;
}
__device__ __forceinline__ void ldsm_x4(uint32_t& r0, uint32_t& r1, uint32_t& r2, uint32_t& r3,
                                        uint32_t addr) {
    asm volatile("ldmatrix.sync.aligned.m8n8.x4.shared.b16 {%0,%1,%2,%3}, [%4];"
                 : "=r"(r0), "=r"(r1), "=r"(r2), "=r"(r3) : "r"(addr));
}
__device__ __forceinline__ void mma_bf16(float* c, uint32_t a0, uint32_t a1, uint32_t a2, uint32_t a3,
                                         uint32_t b0, uint32_t b1) {
    asm volatile("mma.sync.aligned.m16n8k16.row.col.f32.bf16.bf16.f32 "
                 "{%0,%1,%2,%3}, {%4,%5,%6,%7}, {%8,%9}, {%0,%1,%2,%3};"
                 : "+f"(c[0]), "+f"(c[1]), "+f"(c[2]), "+f"(c[3])
                 : "r"(a0), "r"(a1), "r"(a2), "r"(a3), "r"(b0), "r"(b1));
}
__device__ __forceinline__ void cp16(uint32_t dst, const void* src) {
    asm volatile("cp.async.ca.shared.global [%0], [%1], 16;" :: "r"(dst), "l"(src));
}
__device__ __forceinline__ void cp_commit() {
    asm volatile("cp.async.commit_group;" ::: "memory");
}

// ===========================================================================
// im2col(keys) f32 -> bf16: g_kcol[n=b*TK+t][k=ci*3+w]
// ===========================================================================
__global__ __launch_bounds__(256)
void im2col_keys(const float* __restrict__ keys)
{
    const int e = blockIdx.x * 256 + threadIdx.x;    // 3200 * 192
    if (e >= BATCH * TK * 192) return;
    const int n  = e / 192;
    const int kc = (e - n * 192) * 8;
    const int b  = n / TK;
    const int t  = n - b * TK;
    __nv_bfloat16 v[8];
    #pragma unroll
    for (int i = 0; i < 8; i++) {
        const int k  = kc + i;
        const int ci = k / 3;
        const int w  = k - ci * 3;
        const int tg = t + w - 1;
        v[i] = (tg >= 0 && tg < TK) ? __float2bfloat16(keys[((size_t)b * 512 + ci) * TK + tg])
                                    : __float2bfloat16(0.f);
    }
    *reinterpret_cast<uint4*>(&g_kcol[(size_t)n * 1536 + kc]) = *reinterpret_cast<uint4*>(v);
}

// ===========================================================================
// f32 -> bf16 conversion of queries + all weights (one launch).
// ===========================================================================
#define CVT_S1 (BATCH * 80  * TQ)
#define CVT_S2 (1024 * 1536)
#define CVT_S3 (80 * 1024)
#define CVT_S4 (160 * 240)
#define CVT_S5 (80 * 160)
#define CVT_S6 (80 * 80)
#define CVT_O2 (CVT_S1)
#define CVT_O3 (CVT_O2 + CVT_S2)
#define CVT_O4 (CVT_O3 + CVT_S3)
#define CVT_O5 (CVT_O4 + CVT_S4)
#define CVT_O6 (CVT_O5 + CVT_S5)
#define CVT_TOT (CVT_O6 + CVT_S6)

__global__ __launch_bounds__(256)
void convert_all(const float* __restrict__ queries,
                 const float* __restrict__ kW1, const float* __restrict__ kW2,
                 const float* __restrict__ qW1, const float* __restrict__ qW2,
                 const float* __restrict__ qW3)
{
    const long e = ((long)blockIdx.x * 256 + threadIdx.x) * 4;
    if (e >= CVT_TOT) return;
    const float* src; __nv_bfloat16* dst; long off;
    if      (e < CVT_O2) { src = queries; dst = g_qbf;   off = e; }
    else if (e < CVT_O3) { src = kW1;     dst = g_kW1bf; off = e - CVT_O2; }
    else if (e < CVT_O4) { src = kW2;     dst = g_kW2bf; off = e - CVT_O3; }
    else if (e < CVT_O5) { src = qW1;     dst = g_qW1bf; off = e - CVT_O4; }
    else if (e < CVT_O6) { src = qW2;     dst = g_qW2bf; off = e - CVT_O5; }
    else                 { src = qW3;     dst = g_qW3bf; off = e - CVT_O6; }
    const float4 v = *reinterpret_cast<const float4*>(src + off);
    __nv_bfloat162* d2 = reinterpret_cast<__nv_bfloat162*>(dst + off);
    d2[0] = __float22bfloat162_rn(make_float2(v.x, v.y));
    d2[1] = __float22bfloat162_rn(make_float2(v.z, v.w));
}

__global__ __launch_bounds__(256)
void init_kenc(const float* __restrict__ kb2)
{
    const int idx = blockIdx.x * 256 + threadIdx.x;
    if (idx < BATCH * 80 * TK)
        g_kenc[idx] = kb2[(idx / TK) % 80];
}

// ===========================================================================
// keys conv1 (512->1024,k3) + fused pointwise conv2 (1024->80) via split-K.
// cp.async double-buffered. GEMM1: M=1024 K=1536 N=3200, tile 128m x 128n.
// ===========================================================================
#define C1_K   1536
#define C1_LD  72
#define C2_LD  136
// smem: Abuf0@0, Abuf1@18432, Bbuf0@36864, Bbuf1@55296 -> 73728
// phase2 overlay: Sh@0 (34816), W2s@34816 (21760)
#define C1_SMEM 73728

__global__ __launch_bounds__(256)
void conv1_fused(const __nv_bfloat16* __restrict__ kcol, const __nv_bfloat16* __restrict__ W1,
                 const float* __restrict__ bias1, const __nv_bfloat16* __restrict__ W2,
                 float* __restrict__ kenc)
{
    extern __shared__ char dsm[];
    const uint32_t smb = smem_to_u32(dsm);
    const int tid  = threadIdx.x;
    const int wid  = tid >> 5;
    const int lane = tid & 31;
    const int m0 = blockIdx.y * 128;
    const int n0 = blockIdx.x * 128;
    const int warp_m = wid >> 1;
    const int warp_n = wid & 1;

    // prefetch lane geometry: 1024 chunks per operand, 4 per thread
    const int pr_r  = tid >> 1;                 // used as e>>3 pattern below

    auto prefetch = [&](int ch, int buf) {
        const int k0 = ch * 64;
        const uint32_t Ab = smb + buf * 18432;
        const uint32_t Bb = smb + 36864 + buf * 18432;
        #pragma unroll
        for (int j = 0; j < 4; j++) {
            const int e  = tid + 256 * j;
            const int r  = e >> 3;
            const int kq = (e & 7) << 3;
            cp16(Ab + (r * C1_LD + kq) * 2, W1   + (size_t)(m0 + r) * C1_K + k0 + kq);
            cp16(Bb + (r * C1_LD + kq) * 2, kcol + (size_t)(n0 + r) * C1_K + k0 + kq);
        }
        cp_commit();
    };

    float acc[2][8][4];
    #pragma unroll
    for (int mt = 0; mt < 2; mt++)
        #pragma unroll
        for (int nt = 0; nt < 8; nt++)
            #pragma unroll
            for (int i = 0; i < 4; i++) acc[mt][nt][i] = 0.f;

    prefetch(0, 0);
    prefetch(1, 1);

    const uint32_t a_lane = ((warp_m * 32 + (lane & 15)) * C1_LD + (lane >> 4) * 8) * 2;
    const uint32_t b_lane = ((warp_n * 64 + (lane & 15)) * C1_LD + (lane >> 4) * 8) * 2;

    for (int ch = 0; ch < 24; ch++) {
        if (ch < 23) asm volatile("cp.async.wait_group 1;" ::: "memory");
        else         asm volatile("cp.async.wait_group 0;" ::: "memory");
        __syncthreads();

        const int buf = ch & 1;
        const uint32_t a_addr0 = smb + buf * 18432 + a_lane;
        const uint32_t b_addr0 = smb + 36864 + buf * 18432 + b_lane;

        #pragma unroll
        for (int ks = 0; ks < 4; ks++) {
            const uint32_t koff = ks * 32;
            uint32_t a[2][4], b[4][4];
            #pragma unroll
            for (int mt = 0; mt < 2; mt++)
                ldsm_x4(a[mt][0], a[mt][1], a[mt][2], a[mt][3],
                        a_addr0 + mt * 16 * C1_LD * 2 + koff);
            #pragma unroll
            for (int np = 0; np < 4; np++)
                ldsm_x4(b[np][0], b[np][1], b[np][2], b[np][3],
                        b_addr0 + np * 16 * C1_LD * 2 + koff);
            #pragma unroll
            for (int mt = 0; mt < 2; mt++)
                #pragma unroll
                for (int np = 0; np < 4; np++) {
                    mma_bf16(acc[mt][np * 2 + 0], a[mt][0], a[mt][1], a[mt][2], a[mt][3],
                             b[np][0], b[np][2]);
                    mma_bf16(acc[mt][np * 2 + 1], a[mt][0], a[mt][1], a[mt][2], a[mt][3],
                             b[np][1], b[np][3]);
                }
        }
        __syncthreads();
        if (ch + 2 < 24) prefetch(ch + 2, buf);
    }
    (void)pr_r;

    // Phase 2: pointwise conv2 partial, overlaying pipeline buffers
    __nv_bfloat16* Sh  = reinterpret_cast<__nv_bfloat16*>(dsm);            // 128n x 136
    __nv_bfloat16* W2s = reinterpret_cast<__nv_bfloat16*>(dsm + 34816);    // 80 x 136

    #pragma unroll
    for (int mt = 0; mt < 2; mt++) {
        const int col = warp_m * 32 + mt * 16 + (lane >> 2);
        const float bv0 = bias1[m0 + col];
        const float bv1 = bias1[m0 + col + 8];
        #pragma unroll
        for (int nt = 0; nt < 8; nt++) {
            const int nb = warp_n * 64 + nt * 8 + ((lane & 3) << 1);
            #pragma unroll
            for (int cc = 0; cc < 2; cc++) {
                Sh[(nb + cc) * C2_LD + col]     = __float2bfloat16(fmaxf(acc[mt][nt][cc]     + bv0, 0.f));
                Sh[(nb + cc) * C2_LD + col + 8] = __float2bfloat16(fmaxf(acc[mt][nt][2 + cc] + bv1, 0.f));
            }
        }
    }
    for (int e = tid; e < 80 * 32; e += 256) {
        const int r = e >> 5;
        const int q = (e & 31) << 2;
        *reinterpret_cast<uint2*>(&W2s[r * C2_LD + q]) =
            *reinterpret_cast<const uint2*>(W2 + (size_t)r * 1024 + m0 + q);
    }
    __syncthreads();

    const uint32_t sh_addr = smem_to_u32(Sh)  + ((wid * 16 + (lane & 15)) * C2_LD + (lane >> 4) * 8) * 2;
    const uint32_t w2_addr = smem_to_u32(W2s) + ((lane & 15) * C2_LD + (lane >> 4) * 8) * 2;
    float acc2[5][2][4];
    #pragma unroll
    for (int ct = 0; ct < 5; ct++)
        #pragma unroll
        for (int s = 0; s < 2; s++)
            #pragma unroll
            for (int i = 0; i < 4; i++) acc2[ct][s][i] = 0.f;

    #pragma unroll
    for (int ks = 0; ks < 8; ks++) {
        const uint32_t koff = ks * 32;
        uint32_t a0, a1, a2, a3;
        ldsm_x4(a0, a1, a2, a3, sh_addr + koff);
        #pragma unroll
        for (int ct = 0; ct < 5; ct++) {
            uint32_t b0, b1, b2, b3;
            ldsm_x4(b0, b1, b2, b3, w2_addr + ct * 16 * C2_LD * 2 + koff);
            mma_bf16(acc2[ct][0], a0, a1, a2, a3, b0, b2);
            mma_bf16(acc2[ct][1], a0, a1, a2, a3, b1, b3);
        }
    }
    #pragma unroll
    for (int ct = 0; ct < 5; ct++)
        #pragma unroll
        for (int s = 0; s < 2; s++)
            #pragma unroll
            for (int i = 0; i < 4; i++) {
                const int co2 = ct * 16 + s * 8 + ((lane & 3) << 1) + (i & 1);
                const int n   = n0 + wid * 16 + (lane >> 2) + ((i >> 1) << 3);
                const int bb  = n / TK;
                const int t   = n - bb * TK;
                atomicAdd(kenc + ((size_t)bb * 80 + co2) * TK + t, acc2[ct][s][i]);
            }
}

// ===========================================================================
// FUSED query path, 512 threads.
// Stage1 (80->160,k3): 16 warps as 8n x 2co-halves (CT=5).
// Stage2/3: warps 0-7 compute; warps 8-15 prefetch W3s during stage2.
// ===========================================================================
#define QF_SMEM 185856

__global__ __launch_bounds__(512)
void fused_q(const __nv_bfloat16* __restrict__ qbf,
             const __nv_bfloat16* __restrict__ W1, const float* __restrict__ b1,
             const __nv_bfloat16* __restrict__ W2, const float* __restrict__ b2,
             const __nv_bfloat16* __restrict__ W3, const float* __restrict__ b3,
             float* __restrict__ qenc)
{
    extern __shared__ char dsm[];
    __nv_bfloat16* A1  = reinterpret_cast<__nv_bfloat16*>(dsm);            // 128 x 248
    __nv_bfloat16* W1s = reinterpret_cast<__nv_bfloat16*>(dsm + 63488);    // 160 x 248
    __nv_bfloat16* H1  = reinterpret_cast<__nv_bfloat16*>(dsm + 142848);   // 128 x 168
    __nv_bfloat16* W2s = reinterpret_cast<__nv_bfloat16*>(dsm);            // 80 x 168 (over A1)
    __nv_bfloat16* H2  = reinterpret_cast<__nv_bfloat16*>(dsm + 26880);    // 128 x 88 (over A1)
    __nv_bfloat16* W3s = reinterpret_cast<__nv_bfloat16*>(dsm + 49408);    // 80 x 88  (over A1)

    const int tid  = threadIdx.x;
    const int wid  = tid >> 5;
    const int lane = tid & 31;
    const int n0   = blockIdx.x * 128;
    const int rowq = (lane & 15);
    const int kq8  = (lane >> 4) * 8;

    // --- fill A1: im2col(queries) 128 n x 240 k (16 warps) ---
    #pragma unroll
    for (int j = 0; j < 15; j++) {
        const int kl = (tid >> 5) + j * 16;    // 0..239
        const int ci = kl / 3;
        const int w  = kl - ci * 3;
        #pragma unroll
        for (int i = 0; i < 4; i++) {
            const int r  = ((tid & 31) << 2) + i;
            const int n  = n0 + r;
            const int bb = n / TQ;
            const int t  = n - bb * TQ;
            const int tg = t + w - 1;
            __nv_bfloat16 v = __float2bfloat16(0.f);
            if (tg >= 0 && tg < TQ) v = qbf[((size_t)bb * 80 + ci) * TQ + tg];
            A1[r * 248 + kl] = v;
        }
    }
    for (int e = tid; e < 160 * 60; e += 512) {
        const int r = e / 60;
        const int q = (e - r * 60) * 4;
        *reinterpret_cast<uint2*>(&W1s[r * 248 + q]) =
            *reinterpret_cast<const uint2*>(W1 + (size_t)r * 240 + q);
    }
    __syncthreads();

    // --- stage 1: [128n x 160co], K=240; warp = (ng, coh) ---
    {
        const int ng  = wid & 7;
        const int coh = (wid >> 3) * 80;
        const uint32_t a_addr = smem_to_u32(A1)  + ((ng * 16 + rowq) * 248 + kq8) * 2;
        const uint32_t b_addr = smem_to_u32(W1s) + ((coh + rowq) * 248 + kq8) * 2;
        float acc1[5][2][4];
        #pragma unroll
        for (int ct = 0; ct < 5; ct++)
            #pragma unroll
            for (int s = 0; s < 2; s++)
                #pragma unroll
                for (int i = 0; i < 4; i++) acc1[ct][s][i] = 0.f;
        #pragma unroll
        for (int ks = 0; ks < 15; ks++) {
            const uint32_t koff = ks * 32;
            uint32_t a0, a1, a2, a3;
            ldsm_x4(a0, a1, a2, a3, a_addr + koff);
            #pragma unroll
            for (int ct = 0; ct < 5; ct++) {
                uint32_t b0, b1, b2, b3;
                ldsm_x4(b0, b1, b2, b3, b_addr + ct * 16 * 248 * 2 + koff);
                mma_bf16(acc1[ct][0], a0, a1, a2, a3, b0, b2);
                mma_bf16(acc1[ct][1], a0, a1, a2, a3, b1, b3);
            }
        }
        __syncthreads();   // all warps done reading A1/W1s (W2s overlays A1)
        #pragma unroll
        for (int ct = 0; ct < 5; ct++)
            #pragma unroll
            for (int s = 0; s < 2; s++)
                #pragma unroll
                for (int i = 0; i < 4; i++) {
                    const int co = coh + ct * 16 + s * 8 + ((lane & 3) << 1) + (i & 1);
                    const int nl = ng * 16 + (lane >> 2) + ((i >> 1) << 3);
                    H1[nl * 168 + co] = __float2bfloat16(fmaxf(acc1[ct][s][i] + b1[co], 0.f));
                }
    }
    for (int e = tid; e < 80 * 40; e += 512) {
        const int r = e / 40;
        const int q = (e - r * 40) * 4;
        *reinterpret_cast<uint2*>(&W2s[r * 168 + q]) =
            *reinterpret_cast<const uint2*>(W2 + (size_t)r * 160 + q);
    }
    __syncthreads();

    // --- stage 2 (warps 0-7); warps 8-15 fill W3s meanwhile ---
    if (wid >= 8) {
        for (int e = tid - 256; e < 80 * 20; e += 256) {
            const int r = e / 20;
            const int q = (e - r * 20) * 4;
            *reinterpret_cast<uint2*>(&W3s[r * 88 + q]) =
                *reinterpret_cast<const uint2*>(W3 + (size_t)r * 80 + q);
        }
    } else {
        const uint32_t a_addr = smem_to_u32(H1)  + ((wid * 16 + rowq) * 168 + kq8) * 2;
        const uint32_t b_addr = smem_to_u32(W2s) + (rowq * 168 + kq8) * 2;
        float acc2[5][2][4];
        #pragma unroll
        for (int ct = 0; ct < 5; ct++)
            #pragma unroll
            for (int s = 0; s < 2; s++)
                #pragma unroll
                for (int i = 0; i < 4; i++) acc2[ct][s][i] = 0.f;
        #pragma unroll
        for (int ks = 0; ks < 10; ks++) {
            const uint32_t koff = ks * 32;
            uint32_t a0, a1, a2, a3;
            ldsm_x4(a0, a1, a2, a3, a_addr + koff);
            #pragma unroll
            for (int ct = 0; ct < 5; ct++) {
                uint32_t b0, b1, b2, b3;
                ldsm_x4(b0, b1, b2, b3, b_addr + ct * 16 * 168 * 2 + koff);
                mma_bf16(acc2[ct][0], a0, a1, a2, a3, b0, b2);
                mma_bf16(acc2[ct][1], a0, a1, a2, a3, b1, b3);
            }
        }
        #pragma unroll
        for (int ct = 0; ct < 5; ct++)
            #pragma unroll
            for (int s = 0; s < 2; s++)
                #pragma unroll
                for (int i = 0; i < 4; i++) {
                    const int co = ct * 16 + s * 8 + ((lane & 3) << 1) + (i & 1);
                    const int nl = wid * 16 + (lane >> 2) + ((i >> 1) << 3);
                    H2[nl * 88 + co] = __float2bfloat16(fmaxf(acc2[ct][s][i] + b2[co], 0.f));
                }
    }
    __syncthreads();

    // --- stage 3 (warps 0-7) -> qenc f32 ---
    if (wid < 8) {
        const uint32_t a_addr = smem_to_u32(H2)  + ((wid * 16 + rowq) * 88 + kq8) * 2;
        const uint32_t b_addr = smem_to_u32(W3s) + (rowq * 88 + kq8) * 2;
        float acc3[5][2][4];
        #pragma unroll
        for (int ct = 0; ct < 5; ct++)
            #pragma unroll
            for (int s = 0; s < 2; s++)
                #pragma unroll
                for (int i = 0; i < 4; i++) acc3[ct][s][i] = 0.f;
        #pragma unroll
        for (int ks = 0; ks < 5; ks++) {
            const uint32_t koff = ks * 32;
            uint32_t a0, a1, a2, a3;
            ldsm_x4(a0, a1, a2, a3, a_addr + koff);
            #pragma unroll
            for (int ct = 0; ct < 5; ct++) {
                uint32_t b0, b1, b2, b3;
                ldsm_x4(b0, b1, b2, b3, b_addr + ct * 16 * 88 * 2 + koff);
                mma_bf16(acc3[ct][0], a0, a1, a2, a3, b0, b2);
                mma_bf16(acc3[ct][1], a0, a1, a2, a3, b1, b3);
            }
        }
        #pragma unroll
        for (int ct = 0; ct < 5; ct++)
            #pragma unroll
            for (int s = 0; s < 2; s++)
                #pragma unroll
                for (int i = 0; i < 4; i++) {
                    const int co = ct * 16 + s * 8 + ((lane & 3) << 1) + (i & 1);
                    const int n  = n0 + wid * 16 + (lane >> 2) + ((i >> 1) << 3);
                    const int bb = n / TQ;
                    const int t  = n - bb * TQ;
                    qenc[((size_t)bb * 80 + co) * TQ + t] = acc3[ct][s][i] + b3[co];
                }
    }
}

// ---------------------------------------------------------------------------
// Fused attention (unchanged from round 5)
// ---------------------------------------------------------------------------
static __device__ __forceinline__ float warp_max(float v) {
    #pragma unroll
    for (int o = 16; o > 0; o >>= 1) v = fmaxf(v, __shfl_xor_sync(0xffffffffu, v, o));
    return v;
}
static __device__ __forceinline__ float warp_sum(float v) {
    #pragma unroll
    for (int o = 16; o > 0; o >>= 1) v += __shfl_xor_sync(0xffffffffu, v, o);
    return v;
}

__global__ __launch_bounds__(256)
void attn_kernel(const float* __restrict__ qenc, const float* __restrict__ kenc,
                 const float* __restrict__ prior, const unsigned char* __restrict__ mask,
                 float* __restrict__ attn_out, float* __restrict__ logp_out)
{
    extern __shared__ float sm[];
    float* Ks  = sm;
    float* Qs  = sm + 80 * TK;
    float* k2s = Qs + 32 * 81;

    const int b   = blockIdx.y;
    const int q0  = blockIdx.x * 32;
    const int tid = threadIdx.x;

    const float* kb = kenc + (size_t)b * 80 * TK;
    for (int i = tid; i < 80 * TK / 4; i += 256)
        reinterpret_cast<float4*>(Ks)[i] = reinterpret_cast<const float4*>(kb)[i];

    const float* qb = qenc + (size_t)b * 80 * TQ;
    {
        const int ql = tid & 31;
        for (int c = tid >> 5; c < 80; c += 8)
            Qs[ql * 81 + c] = qb[c * TQ + q0 + ql];
    }
    __syncthreads();

    for (int k = tid; k < TK; k += 256) {
        float s = 0.f;
        #pragma unroll 8
        for (int c = 0; c < 80; c++) { const float v = Ks[c * TK + k]; s = fmaf(v, v, s); }
        k2s[k] = s;
    }
    __syncthreads();

    const int warp = tid >> 5, lane = tid & 31;
    constexpr int KI = 7;

    float s[4][KI];
    #pragma unroll
    for (int r = 0; r < 4; r++)
        #pragma unroll
        for (int i = 0; i < KI; i++) s[r][i] = 0.f;

    for (int c = 0; c < 80; c++) {
        float qv[4];
        #pragma unroll
        for (int r = 0; r < 4; r++) qv[r] = Qs[(warp * 4 + r) * 81 + c];
        float kv[KI];
        #pragma unroll
        for (int i = 0; i < 6; i++) kv[i] = Ks[c * TK + lane + 32 * i];
        kv[6] = (lane < 8) ? Ks[c * TK + lane + 192] : 0.f;
        #pragma unroll
        for (int r = 0; r < 4; r++)
            #pragma unroll
            for (int i = 0; i < KI; i++)
                s[r][i] = fmaf(qv[r], kv[i], s[r][i]);
    }

    const float NEG_INF = -CUDART_INF_F;
    #pragma unroll
    for (int r = 0; r < 4; r++) {
        const int q = q0 + warp * 4 + r;
        const size_t row = ((size_t)b * TQ + q) * TK;

        float m1 = NEG_INF;
        #pragma unroll
        for (int i = 0; i < KI; i++) {
            const int k = lane + 32 * i;
            const float sc = (k < TK) ? -5e-4f * (k2s[k] - 2.f * s[r][i]) : NEG_INF;
            s[r][i] = sc;
            m1 = fmaxf(m1, sc);
        }
        m1 = warp_max(m1);

        float e[KI];
        float se = 0.f;
        #pragma unroll
        for (int i = 0; i < KI; i++) {
            const int k = lane + 32 * i;
            if (k < TK) { e[i] = __expf(s[r][i] - m1); se += e[i]; }
        }
        se = warp_sum(se);
        const float lse = m1 + __logf(se);

        float se2 = 0.f;
        #pragma unroll
        for (int i = 0; i < KI; i++) {
            const int k = lane + 32 * i;
            if (k < TK) {
                const float pr = prior[row + k] + 1e-8f;
                logp_out[row + k] = s[r][i] - lse + __logf(pr);
                const float wv = mask[b * TK + k] ? 0.f : e[i] * pr;
                e[i] = wv;
                se2 += wv;
            }
        }
        se2 = warp_sum(se2);
        const float inv = 1.f / se2;
        #pragma unroll
        for (int i = 0; i < KI; i++) {
            const int k = lane + 32 * i;
            if (k < TK) attn_out[row + k] = e[i] * inv;
        }
    }
}

// ---------------------------------------------------------------------------
extern "C" void kernel_launch(void* const* d_in, const int* in_sizes, int n_in,
                              void* d_out, int out_size)
{
    const float* queries = (const float*)d_in[0];
    const float* keys    = (const float*)d_in[1];
    const unsigned char* mask = (const unsigned char*)d_in[3];
    const float* prior   = (const float*)d_in[4];
    const float* kW1 = (const float*)d_in[5];
    const float* kb1 = (const float*)d_in[6];
    const float* kW2 = (const float*)d_in[7];
    const float* kb2 = (const float*)d_in[8];
    const float* qW1 = (const float*)d_in[9];
    const float* qb1 = (const float*)d_in[10];
    const float* qW2 = (const float*)d_in[11];
    const float* qb2 = (const float*)d_in[12];
    const float* qW3 = (const float*)d_in[13];
    const float* qb3 = (const float*)d_in[14];

    float* out      = (float*)d_out;
    float* attn_out = out;
    float* logp_out = out + (size_t)BATCH * TQ * TK;

    __nv_bfloat16 *kcol, *qbf, *kW1bf, *kW2bf, *qW1bf, *qW2bf, *qW3bf;
    float *kenc, *qenc;
    cudaGetSymbolAddress((void**)&kcol,  g_kcol);
    cudaGetSymbolAddress((void**)&qbf,   g_qbf);
    cudaGetSymbolAddress((void**)&kW1bf, g_kW1bf);
    cudaGetSymbolAddress((void**)&kW2bf, g_kW2bf);
    cudaGetSymbolAddress((void**)&qW1bf, g_qW1bf);
    cudaGetSymbolAddress((void**)&qW2bf, g_qW2bf);
    cudaGetSymbolAddress((void**)&qW3bf, g_qW3bf);
    cudaGetSymbolAddress((void**)&kenc,  g_kenc);
    cudaGetSymbolAddress((void**)&qenc,  g_qenc);

    // 0) operand prep
    im2col_keys<<<(BATCH * TK * 192 + 255) / 256, 256>>>(keys);
    convert_all<<<(CVT_TOT / 4 + 255) / 256, 256>>>(queries, kW1, kW2, qW1, qW2, qW3);
    init_kenc<<<(BATCH * 80 * TK + 255) / 256, 256>>>(kb2);

    // 1) keys conv1 + fused pointwise conv2 (cp.async pipelined)
    cudaFuncSetAttribute(conv1_fused, cudaFuncAttributeMaxDynamicSharedMemorySize, C1_SMEM);
    conv1_fused<<<dim3(BATCH * TK / 128, 1024 / 128), 256, C1_SMEM>>>(kcol, kW1bf, kb1, kW2bf, kenc);

    // 2) fused query path (512 threads)
    cudaFuncSetAttribute(fused_q, cudaFuncAttributeMaxDynamicSharedMemorySize, QF_SMEM);
    fused_q<<<BATCH * TQ / 128, 512, QF_SMEM>>>(qbf, qW1bf, qb1, qW2bf, qb2, qW3bf, qb3, qenc);

    // 3) fused attention
    const int smem = (80 * TK + 32 * 81 + TK) * (int)sizeof(float);
    cudaFuncSetAttribute(attn_kernel, cudaFuncAttributeMaxDynamicSharedMemorySize, smem);
    attn_kernel<<<dim3(TQ / 32, BATCH), 256, smem>>>(qenc, kenc, prior, mask, attn_out, logp_out);
}

// round 7
// speedup vs baseline: 2.7977x; 1.0224x over previous
#include <cuda_runtime.h>
#include <cuda_bf16.h>
#include <math_constants.h>
#include <cstdint>
#include <cstddef>

#define BATCH 16
#define TQ 800
#define TK 200

// ---------------------------------------------------------------------------
// Device-global scratch (no allocations allowed)
// ---------------------------------------------------------------------------
__device__ __align__(16) __nv_bfloat16 g_kcol [BATCH * TK * 1536];   // im2col(keys)
__device__ __align__(16) __nv_bfloat16 g_qbf  [BATCH * 80  * TQ];
__device__ __align__(16) __nv_bfloat16 g_kW1bf[1024 * 1536];
__device__ __align__(16) __nv_bfloat16 g_kW2bf[80 * 1024];
__device__ __align__(16) __nv_bfloat16 g_qW1bf[160 * 240];
__device__ __align__(16) __nv_bfloat16 g_qW2bf[80 * 160];
__device__ __align__(16) __nv_bfloat16 g_qW3bf[80 * 80];
__device__ float g_kenc[BATCH * 80 * TK];
__device__ float g_qenc[BATCH * 80 * TQ];

__device__ __forceinline__ uint32_t smem_to_u32(const void* p) {
    uint32_t a;
    asm("{ .reg .u64 t; cvta.to.shared.u64 t, %1; cvt.u32.u64 %0, t; }" : "=r"(a) : "l"(p));
    return a;
}
__device__ __forceinline__ void ldsm_x4(uint32_t& r0, uint32_t& r1, uint32_t& r2, uint32_t& r3,
                                        uint32_t addr) {
    asm volatile("ldmatrix.sync.aligned.m8n8.x4.shared.b16 {%0,%1,%2,%3}, [%4];"
                 : "=r"(r0), "=r"(r1), "=r"(r2), "=r"(r3) : "r"(addr));
}
__device__ __forceinline__ void mma_bf16(float* c, uint32_t a0, uint32_t a1, uint32_t a2, uint32_t a3,
                                         uint32_t b0, uint32_t b1) {
    asm volatile("mma.sync.aligned.m16n8k16.row.col.f32.bf16.bf16.f32 "
                 "{%0,%1,%2,%3}, {%4,%5,%6,%7}, {%8,%9}, {%0,%1,%2,%3};"
                 : "+f"(c[0]), "+f"(c[1]), "+f"(c[2]), "+f"(c[3])
                 : "r"(a0), "r"(a1), "r"(a2), "r"(a3), "r"(b0), "r"(b1));
}
__device__ __forceinline__ void cp16(uint32_t dst, const void* src) {
    asm volatile("cp.async.ca.shared.global [%0], [%1], 16;" :: "r"(dst), "l"(src));
}
__device__ __forceinline__ void cp_commit() {
    asm volatile("cp.async.commit_group;" ::: "memory");
}

// ===========================================================================
// im2col(keys) f32 -> bf16: g_kcol[n=b*TK+t][k=ci*3+w]
// ===========================================================================
__global__ __launch_bounds__(256)
void im2col_keys(const float* __restrict__ keys)
{
    const int e = blockIdx.x * 256 + threadIdx.x;    // 3200 * 192
    if (e >= BATCH * TK * 192) return;
    const int n  = e / 192;
    const int kc = (e - n * 192) * 8;
    const int b  = n / TK;
    const int t  = n - b * TK;
    __nv_bfloat16 v[8];
    #pragma unroll
    for (int i = 0; i < 8; i++) {
        const int k  = kc + i;
        const int ci = k / 3;
        const int w  = k - ci * 3;
        const int tg = t + w - 1;
        v[i] = (tg >= 0 && tg < TK) ? __float2bfloat16(keys[((size_t)b * 512 + ci) * TK + tg])
                                    : __float2bfloat16(0.f);
    }
    *reinterpret_cast<uint4*>(&g_kcol[(size_t)n * 1536 + kc]) = *reinterpret_cast<uint4*>(v);
}

// ===========================================================================
// f32 -> bf16 conversion of queries + all weights (one launch).
// ===========================================================================
#define CVT_S1 (BATCH * 80  * TQ)
#define CVT_S2 (1024 * 1536)
#define CVT_S3 (80 * 1024)
#define CVT_S4 (160 * 240)
#define CVT_S5 (80 * 160)
#define CVT_S6 (80 * 80)
#define CVT_O2 (CVT_S1)
#define CVT_O3 (CVT_O2 + CVT_S2)
#define CVT_O4 (CVT_O3 + CVT_S3)
#define CVT_O5 (CVT_O4 + CVT_S4)
#define CVT_O6 (CVT_O5 + CVT_S5)
#define CVT_TOT (CVT_O6 + CVT_S6)

__global__ __launch_bounds__(256)
void convert_all(const float* __restrict__ queries,
                 const float* __restrict__ kW1, const float* __restrict__ kW2,
                 const float* __restrict__ qW1, const float* __restrict__ qW2,
                 const float* __restrict__ qW3)
{
    const long e = ((long)blockIdx.x * 256 + threadIdx.x) * 4;
    if (e >= CVT_TOT) return;
    const float* src; __nv_bfloat16* dst; long off;
    if      (e < CVT_O2) { src = queries; dst = g_qbf;   off = e; }
    else if (e < CVT_O3) { src = kW1;     dst = g_kW1bf; off = e - CVT_O2; }
    else if (e < CVT_O4) { src = kW2;     dst = g_kW2bf; off = e - CVT_O3; }
    else if (e < CVT_O5) { src = qW1;     dst = g_qW1bf; off = e - CVT_O4; }
    else if (e < CVT_O6) { src = qW2;     dst = g_qW2bf; off = e - CVT_O5; }
    else                 { src = qW3;     dst = g_qW3bf; off = e - CVT_O6; }
    const float4 v = *reinterpret_cast<const float4*>(src + off);
    __nv_bfloat162* d2 = reinterpret_cast<__nv_bfloat162*>(dst + off);
    d2[0] = __float22bfloat162_rn(make_float2(v.x, v.y));
    d2[1] = __float22bfloat162_rn(make_float2(v.z, v.w));
}

__global__ __launch_bounds__(256)
void init_kenc(const float* __restrict__ kb2)
{
    const int idx = blockIdx.x * 256 + threadIdx.x;
    if (idx < BATCH * 80 * TK)
        g_kenc[idx] = kb2[(idx / TK) % 80];
}

// ===========================================================================
// keys conv1 (512->1024,k3) + fused pointwise conv2 (1024->80) via split-K.
// Tile 128m x 64n, grid 400 (8m x 50n). 3-stage cp.async, 1 sync per chunk.
// 8 warps as 4m x 2n; warp tile 32m x 32n.
// ===========================================================================
#define C1_K   1536
#define C1_LD  72
#define C2_LD  136
// smem: A stages 3 x 18432 @0, B stages 3 x 9216 @55296 -> 82944
// phase2 overlay: Sh[64n x 136] @0 (17408), W2s[80 x 136] @17408 (21760)
#define C1_SMEM 82944

__global__ __launch_bounds__(256)
void conv1_fused(const __nv_bfloat16* __restrict__ kcol, const __nv_bfloat16* __restrict__ W1,
                 const float* __restrict__ bias1, const __nv_bfloat16* __restrict__ W2,
                 float* __restrict__ kenc)
{
    extern __shared__ char dsm[];
    const uint32_t smb = smem_to_u32(dsm);
    const int tid  = threadIdx.x;
    const int wid  = tid >> 5;
    const int lane = tid & 31;
    const int m0 = blockIdx.y * 128;
    const int n0 = blockIdx.x * 64;
    const int warp_m = wid >> 1;   // 0..3 -> 32 m-rows each
    const int warp_n = wid & 1;    // 0..1 -> 32 n-rows each

    auto prefetch = [&](int ch, int st) {
        const int k0 = ch * 64;
        const uint32_t Ab = smb + st * 18432;
        const uint32_t Bb = smb + 55296 + st * 9216;
        #pragma unroll
        for (int j = 0; j < 4; j++) {          // A: 1024 16B chunks
            const int e  = tid + 256 * j;
            const int r  = e >> 3;
            const int kq = (e & 7) << 3;
            cp16(Ab + (r * C1_LD + kq) * 2, W1 + (size_t)(m0 + r) * C1_K + k0 + kq);
        }
        #pragma unroll
        for (int j = 0; j < 2; j++) {          // B: 512 16B chunks
            const int e  = tid + 256 * j;
            const int r  = e >> 3;
            const int kq = (e & 7) << 3;
            cp16(Bb + (r * C1_LD + kq) * 2, kcol + (size_t)(n0 + r) * C1_K + k0 + kq);
        }
        cp_commit();
    };

    float acc[2][4][4];
    #pragma unroll
    for (int mt = 0; mt < 2; mt++)
        #pragma unroll
        for (int nt = 0; nt < 4; nt++)
            #pragma unroll
            for (int i = 0; i < 4; i++) acc[mt][nt][i] = 0.f;

    prefetch(0, 0);
    prefetch(1, 1);

    const uint32_t a_lane = ((warp_m * 32 + (lane & 15)) * C1_LD + (lane >> 4) * 8) * 2;
    const uint32_t b_lane = ((warp_n * 32 + (lane & 15)) * C1_LD + (lane >> 4) * 8) * 2;

    for (int ch = 0; ch < 24; ch++) {
        if (ch < 23) asm volatile("cp.async.wait_group 1;" ::: "memory");
        else         asm volatile("cp.async.wait_group 0;" ::: "memory");
        __syncthreads();

        const int st = ch % 3;
        const uint32_t a_addr0 = smb + st * 18432 + a_lane;
        const uint32_t b_addr0 = smb + 55296 + st * 9216 + b_lane;

        #pragma unroll
        for (int ks = 0; ks < 4; ks++) {
            const uint32_t koff = ks * 32;
            uint32_t a[2][4], b[2][4];
            #pragma unroll
            for (int mt = 0; mt < 2; mt++)
                ldsm_x4(a[mt][0], a[mt][1], a[mt][2], a[mt][3],
                        a_addr0 + mt * 16 * C1_LD * 2 + koff);
            #pragma unroll
            for (int np = 0; np < 2; np++)
                ldsm_x4(b[np][0], b[np][1], b[np][2], b[np][3],
                        b_addr0 + np * 16 * C1_LD * 2 + koff);
            #pragma unroll
            for (int mt = 0; mt < 2; mt++)
                #pragma unroll
                for (int np = 0; np < 2; np++) {
                    mma_bf16(acc[mt][np * 2 + 0], a[mt][0], a[mt][1], a[mt][2], a[mt][3],
                             b[np][0], b[np][2]);
                    mma_bf16(acc[mt][np * 2 + 1], a[mt][0], a[mt][1], a[mt][2], a[mt][3],
                             b[np][1], b[np][3]);
                }
        }
        // prefetch into the stage retired at this iteration's barrier
        if (ch + 2 < 24) prefetch(ch + 2, (ch + 2) % 3);
    }
    __syncthreads();   // everyone done with pipeline buffers

    // Phase 2: pointwise conv2 partial, overlaying pipeline buffers
    __nv_bfloat16* Sh  = reinterpret_cast<__nv_bfloat16*>(dsm);            // 64n x 136
    __nv_bfloat16* W2s = reinterpret_cast<__nv_bfloat16*>(dsm + 17408);    // 80 x 136

    #pragma unroll
    for (int mt = 0; mt < 2; mt++) {
        const int col = warp_m * 32 + mt * 16 + (lane >> 2);
        const float bv0 = bias1[m0 + col];
        const float bv1 = bias1[m0 + col + 8];
        #pragma unroll
        for (int nt = 0; nt < 4; nt++) {
            const int nb = warp_n * 32 + (nt >> 1) * 16 + (nt & 1) * 8 + ((lane & 3) << 1);
            #pragma unroll
            for (int cc = 0; cc < 2; cc++) {
                Sh[(nb + cc) * C2_LD + col]     = __float2bfloat16(fmaxf(acc[mt][nt][cc]     + bv0, 0.f));
                Sh[(nb + cc) * C2_LD + col + 8] = __float2bfloat16(fmaxf(acc[mt][nt][2 + cc] + bv1, 0.f));
            }
        }
    }
    for (int e = tid; e < 80 * 32; e += 256) {
        const int r = e >> 5;
        const int q = (e & 31) << 2;
        *reinterpret_cast<uint2*>(&W2s[r * C2_LD + q]) =
            *reinterpret_cast<const uint2*>(W2 + (size_t)r * 1024 + m0 + q);
    }
    __syncthreads();

    // GEMM2: [64n x 80co2] over K=128 local couts; warps 0-3, 16 n-rows each
    if (wid < 4) {
        const uint32_t sh_addr = smem_to_u32(Sh)  + ((wid * 16 + (lane & 15)) * C2_LD + (lane >> 4) * 8) * 2;
        const uint32_t w2_addr = smem_to_u32(W2s) + ((lane & 15) * C2_LD + (lane >> 4) * 8) * 2;
        float acc2[5][2][4];
        #pragma unroll
        for (int ct = 0; ct < 5; ct++)
            #pragma unroll
            for (int s = 0; s < 2; s++)
                #pragma unroll
                for (int i = 0; i < 4; i++) acc2[ct][s][i] = 0.f;

        #pragma unroll
        for (int ks = 0; ks < 8; ks++) {
            const uint32_t koff = ks * 32;
            uint32_t a0, a1, a2, a3;
            ldsm_x4(a0, a1, a2, a3, sh_addr + koff);
            #pragma unroll
            for (int ct = 0; ct < 5; ct++) {
                uint32_t b0, b1, b2, b3;
                ldsm_x4(b0, b1, b2, b3, w2_addr + ct * 16 * C2_LD * 2 + koff);
                mma_bf16(acc2[ct][0], a0, a1, a2, a3, b0, b2);
                mma_bf16(acc2[ct][1], a0, a1, a2, a3, b1, b3);
            }
        }
        #pragma unroll
        for (int ct = 0; ct < 5; ct++)
            #pragma unroll
            for (int s = 0; s < 2; s++)
                #pragma unroll
                for (int i = 0; i < 4; i++) {
                    const int co2 = ct * 16 + s * 8 + ((lane & 3) << 1) + (i & 1);
                    const int n   = n0 + wid * 16 + (lane >> 2) + ((i >> 1) << 3);
                    const int bb  = n / TK;
                    const int t   = n - bb * TK;
                    atomicAdd(kenc + ((size_t)bb * 80 + co2) * TK + t, acc2[ct][s][i]);
                }
    }
}

// ===========================================================================
// FUSED query path, 512 threads (unchanged from round 6).
// ===========================================================================
#define QF_SMEM 185856

__global__ __launch_bounds__(512)
void fused_q(const __nv_bfloat16* __restrict__ qbf,
             const __nv_bfloat16* __restrict__ W1, const float* __restrict__ b1,
             const __nv_bfloat16* __restrict__ W2, const float* __restrict__ b2,
             const __nv_bfloat16* __restrict__ W3, const float* __restrict__ b3,
             float* __restrict__ qenc)
{
    extern __shared__ char dsm[];
    __nv_bfloat16* A1  = reinterpret_cast<__nv_bfloat16*>(dsm);            // 128 x 248
    __nv_bfloat16* W1s = reinterpret_cast<__nv_bfloat16*>(dsm + 63488);    // 160 x 248
    __nv_bfloat16* H1  = reinterpret_cast<__nv_bfloat16*>(dsm + 142848);   // 128 x 168
    __nv_bfloat16* W2s = reinterpret_cast<__nv_bfloat16*>(dsm);            // 80 x 168 (over A1)
    __nv_bfloat16* H2  = reinterpret_cast<__nv_bfloat16*>(dsm + 26880);    // 128 x 88 (over A1)
    __nv_bfloat16* W3s = reinterpret_cast<__nv_bfloat16*>(dsm + 49408);    // 80 x 88  (over A1)

    const int tid  = threadIdx.x;
    const int wid  = tid >> 5;
    const int lane = tid & 31;
    const int n0   = blockIdx.x * 128;
    const int rowq = (lane & 15);
    const int kq8  = (lane >> 4) * 8;

    #pragma unroll
    for (int j = 0; j < 15; j++) {
        const int kl = (tid >> 5) + j * 16;
        const int ci = kl / 3;
        const int w  = kl - ci * 3;
        #pragma unroll
        for (int i = 0; i < 4; i++) {
            const int r  = ((tid & 31) << 2) + i;
            const int n  = n0 + r;
            const int bb = n / TQ;
            const int t  = n - bb * TQ;
            const int tg = t + w - 1;
            __nv_bfloat16 v = __float2bfloat16(0.f);
            if (tg >= 0 && tg < TQ) v = qbf[((size_t)bb * 80 + ci) * TQ + tg];
            A1[r * 248 + kl] = v;
        }
    }
    for (int e = tid; e < 160 * 60; e += 512) {
        const int r = e / 60;
        const int q = (e - r * 60) * 4;
        *reinterpret_cast<uint2*>(&W1s[r * 248 + q]) =
            *reinterpret_cast<const uint2*>(W1 + (size_t)r * 240 + q);
    }
    __syncthreads();

    {
        const int ng  = wid & 7;
        const int coh = (wid >> 3) * 80;
        const uint32_t a_addr = smem_to_u32(A1)  + ((ng * 16 + rowq) * 248 + kq8) * 2;
        const uint32_t b_addr = smem_to_u32(W1s) + ((coh + rowq) * 248 + kq8) * 2;
        float acc1[5][2][4];
        #pragma unroll
        for (int ct = 0; ct < 5; ct++)
            #pragma unroll
            for (int s = 0; s < 2; s++)
                #pragma unroll
                for (int i = 0; i < 4; i++) acc1[ct][s][i] = 0.f;
        #pragma unroll
        for (int ks = 0; ks < 15; ks++) {
            const uint32_t koff = ks * 32;
            uint32_t a0, a1, a2, a3;
            ldsm_x4(a0, a1, a2, a3, a_addr + koff);
            #pragma unroll
            for (int ct = 0; ct < 5; ct++) {
                uint32_t b0, b1, b2, b3;
                ldsm_x4(b0, b1, b2, b3, b_addr + ct * 16 * 248 * 2 + koff);
                mma_bf16(acc1[ct][0], a0, a1, a2, a3, b0, b2);
                mma_bf16(acc1[ct][1], a0, a1, a2, a3, b1, b3);
            }
        }
        __syncthreads();
        #pragma unroll
        for (int ct = 0; ct < 5; ct++)
            #pragma unroll
            for (int s = 0; s < 2; s++)
                #pragma unroll
                for (int i = 0; i < 4; i++) {
                    const int co = coh + ct * 16 + s * 8 + ((lane & 3) << 1) + (i & 1);
                    const int nl = ng * 16 + (lane >> 2) + ((i >> 1) << 3);
                    H1[nl * 168 + co] = __float2bfloat16(fmaxf(acc1[ct][s][i] + b1[co], 0.f));
                }
    }
    for (int e = tid; e < 80 * 40; e += 512) {
        const int r = e / 40;
        const int q = (e - r * 40) * 4;
        *reinterpret_cast<uint2*>(&W2s[r * 168 + q]) =
            *reinterpret_cast<const uint2*>(W2 + (size_t)r * 160 + q);
    }
    __syncthreads();

    if (wid >= 8) {
        for (int e = tid - 256; e < 80 * 20; e += 256) {
            const int r = e / 20;
            const int q = (e - r * 20) * 4;
            *reinterpret_cast<uint2*>(&W3s[r * 88 + q]) =
                *reinterpret_cast<const uint2*>(W3 + (size_t)r * 80 + q);
        }
    } else {
        const uint32_t a_addr = smem_to_u32(H1)  + ((wid * 16 + rowq) * 168 + kq8) * 2;
        const uint32_t b_addr = smem_to_u32(W2s) + (rowq * 168 + kq8) * 2;
        float acc2[5][2][4];
        #pragma unroll
        for (int ct = 0; ct < 5; ct++)
            #pragma unroll
            for (int s = 0; s < 2; s++)
                #pragma unroll
                for (int i = 0; i < 4; i++) acc2[ct][s][i] = 0.f;
        #pragma unroll
        for (int ks = 0; ks < 10; ks++) {
            const uint32_t koff = ks * 32;
            uint32_t a0, a1, a2, a3;
            ldsm_x4(a0, a1, a2, a3, a_addr + koff);
            #pragma unroll
            for (int ct = 0; ct < 5; ct++) {
                uint32_t b0, b1, b2, b3;
                ldsm_x4(b0, b1, b2, b3, b_addr + ct * 16 * 168 * 2 + koff);
                mma_bf16(acc2[ct][0], a0, a1, a2, a3, b0, b2);
                mma_bf16(acc2[ct][1], a0, a1, a2, a3, b1, b3);
            }
        }
        #pragma unroll
        for (int ct = 0; ct < 5; ct++)
            #pragma unroll
            for (int s = 0; s < 2; s++)
                #pragma unroll
                for (int i = 0; i < 4; i++) {
                    const int co = ct * 16 + s * 8 + ((lane & 3) << 1) + (i & 1);
                    const int nl = wid * 16 + (lane >> 2) + ((i >> 1) << 3);
                    H2[nl * 88 + co] = __float2bfloat16(fmaxf(acc2[ct][s][i] + b2[co], 0.f));
                }
    }
    __syncthreads();

    if (wid < 8) {
        const uint32_t a_addr = smem_to_u32(H2)  + ((wid * 16 + rowq) * 88 + kq8) * 2;
        const uint32_t b_addr = smem_to_u32(W3s) + (rowq * 88 + kq8) * 2;
        float acc3[5][2][4];
        #pragma unroll
        for (int ct = 0; ct < 5; ct++)
            #pragma unroll
            for (int s = 0; s < 2; s++)
                #pragma unroll
                for (int i = 0; i < 4; i++) acc3[ct][s][i] = 0.f;
        #pragma unroll
        for (int ks = 0; ks < 5; ks++) {
            const uint32_t koff = ks * 32;
            uint32_t a0, a1, a2, a3;
            ldsm_x4(a0, a1, a2, a3, a_addr + koff);
            #pragma unroll
            for (int ct = 0; ct < 5; ct++) {
                uint32_t b0, b1, b2, b3;
                ldsm_x4(b0, b1, b2, b3, b_addr + ct * 16 * 88 * 2 + koff);
                mma_bf16(acc3[ct][0], a0, a1, a2, a3, b0, b2);
                mma_bf16(acc3[ct][1], a0, a1, a2, a3, b1, b3);
            }
        }
        #pragma unroll
        for (int ct = 0; ct < 5; ct++)
            #pragma unroll
            for (int s = 0; s < 2; s++)
                #pragma unroll
                for (int i = 0; i < 4; i++) {
                    const int co = ct * 16 + s * 8 + ((lane & 3) << 1) + (i & 1);
                    const int n  = n0 + wid * 16 + (lane >> 2) + ((i >> 1) << 3);
                    const int bb = n / TQ;
                    const int t  = n - bb * TQ;
                    qenc[((size_t)bb * 80 + co) * TQ + t] = acc3[ct][s][i] + b3[co];
                }
    }
}

// ---------------------------------------------------------------------------
// Fused attention (unchanged)
// ---------------------------------------------------------------------------
static __device__ __forceinline__ float warp_max(float v) {
    #pragma unroll
    for (int o = 16; o > 0; o >>= 1) v = fmaxf(v, __shfl_xor_sync(0xffffffffu, v, o));
    return v;
}
static __device__ __forceinline__ float warp_sum(float v) {
    #pragma unroll
    for (int o = 16; o > 0; o >>= 1) v += __shfl_xor_sync(0xffffffffu, v, o);
    return v;
}

__global__ __launch_bounds__(256)
void attn_kernel(const float* __restrict__ qenc, const float* __restrict__ kenc,
                 const float* __restrict__ prior, const unsigned char* __restrict__ mask,
                 float* __restrict__ attn_out, float* __restrict__ logp_out)
{
    extern __shared__ float sm[];
    float* Ks  = sm;
    float* Qs  = sm + 80 * TK;
    float* k2s = Qs + 32 * 81;

    const int b   = blockIdx.y;
    const int q0  = blockIdx.x * 32;
    const int tid = threadIdx.x;

    const float* kb = kenc + (size_t)b * 80 * TK;
    for (int i = tid; i < 80 * TK / 4; i += 256)
        reinterpret_cast<float4*>(Ks)[i] = reinterpret_cast<const float4*>(kb)[i];

    const float* qb = qenc + (size_t)b * 80 * TQ;
    {
        const int ql = tid & 31;
        for (int c = tid >> 5; c < 80; c += 8)
            Qs[ql * 81 + c] = qb[c * TQ + q0 + ql];
    }
    __syncthreads();

    for (int k = tid; k < TK; k += 256) {
        float s = 0.f;
        #pragma unroll 8
        for (int c = 0; c < 80; c++) { const float v = Ks[c * TK + k]; s = fmaf(v, v, s); }
        k2s[k] = s;
    }
    __syncthreads();

    const int warp = tid >> 5, lane = tid & 31;
    constexpr int KI = 7;

    float s[4][KI];
    #pragma unroll
    for (int r = 0; r < 4; r++)
        #pragma unroll
        for (int i = 0; i < KI; i++) s[r][i] = 0.f;

    for (int c = 0; c < 80; c++) {
        float qv[4];
        #pragma unroll
        for (int r = 0; r < 4; r++) qv[r] = Qs[(warp * 4 + r) * 81 + c];
        float kv[KI];
        #pragma unroll
        for (int i = 0; i < 6; i++) kv[i] = Ks[c * TK + lane + 32 * i];
        kv[6] = (lane < 8) ? Ks[c * TK + lane + 192] : 0.f;
        #pragma unroll
        for (int r = 0; r < 4; r++)
            #pragma unroll
            for (int i = 0; i < KI; i++)
                s[r][i] = fmaf(qv[r], kv[i], s[r][i]);
    }

    const float NEG_INF = -CUDART_INF_F;
    #pragma unroll
    for (int r = 0; r < 4; r++) {
        const int q = q0 + warp * 4 + r;
        const size_t row = ((size_t)b * TQ + q) * TK;

        float m1 = NEG_INF;
        #pragma unroll
        for (int i = 0; i < KI; i++) {
            const int k = lane + 32 * i;
            const float sc = (k < TK) ? -5e-4f * (k2s[k] - 2.f * s[r][i]) : NEG_INF;
            s[r][i] = sc;
            m1 = fmaxf(m1, sc);
        }
        m1 = warp_max(m1);

        float e[KI];
        float se = 0.f;
        #pragma unroll
        for (int i = 0; i < KI; i++) {
            const int k = lane + 32 * i;
            if (k < TK) { e[i] = __expf(s[r][i] - m1); se += e[i]; }
        }
        se = warp_sum(se);
        const float lse = m1 + __logf(se);

        float se2 = 0.f;
        #pragma unroll
        for (int i = 0; i < KI; i++) {
            const int k = lane + 32 * i;
            if (k < TK) {
                const float pr = prior[row + k] + 1e-8f;
                logp_out[row + k] = s[r][i] - lse + __logf(pr);
                const float wv = mask[b * TK + k] ? 0.f : e[i] * pr;
                e[i] = wv;
                se2 += wv;
            }
        }
        se2 = warp_sum(se2);
        const float inv = 1.f / se2;
        #pragma unroll
        for (int i = 0; i < KI; i++) {
            const int k = lane + 32 * i;
            if (k < TK) attn_out[row + k] = e[i] * inv;
        }
    }
}

// ---------------------------------------------------------------------------
extern "C" void kernel_launch(void* const* d_in, const int* in_sizes, int n_in,
                              void* d_out, int out_size)
{
    const float* queries = (const float*)d_in[0];
    const float* keys    = (const float*)d_in[1];
    const unsigned char* mask = (const unsigned char*)d_in[3];
    const float* prior   = (const float*)d_in[4];
    const float* kW1 = (const float*)d_in[5];
    const float* kb1 = (const float*)d_in[6];
    const float* kW2 = (const float*)d_in[7];
    const float* kb2 = (const float*)d_in[8];
    const float* qW1 = (const float*)d_in[9];
    const float* qb1 = (const float*)d_in[10];
    const float* qW2 = (const float*)d_in[11];
    const float* qb2 = (const float*)d_in[12];
    const float* qW3 = (const float*)d_in[13];
    const float* qb3 = (const float*)d_in[14];

    float* out      = (float*)d_out;
    float* attn_out = out;
    float* logp_out = out + (size_t)BATCH * TQ * TK;

    __nv_bfloat16 *kcol, *qbf, *kW1bf, *kW2bf, *qW1bf, *qW2bf, *qW3bf;
    float *kenc, *qenc;
    cudaGetSymbolAddress((void**)&kcol,  g_kcol);
    cudaGetSymbolAddress((void**)&qbf,   g_qbf);
    cudaGetSymbolAddress((void**)&kW1bf, g_kW1bf);
    cudaGetSymbolAddress((void**)&kW2bf, g_kW2bf);
    cudaGetSymbolAddress((void**)&qW1bf, g_qW1bf);
    cudaGetSymbolAddress((void**)&qW2bf, g_qW2bf);
    cudaGetSymbolAddress((void**)&qW3bf, g_qW3bf);
    cudaGetSymbolAddress((void**)&kenc,  g_kenc);
    cudaGetSymbolAddress((void**)&qenc,  g_qenc);

    // 0) operand prep
    im2col_keys<<<(BATCH * TK * 192 + 255) / 256, 256>>>(keys);
    convert_all<<<(CVT_TOT / 4 + 255) / 256, 256>>>(queries, kW1, kW2, qW1, qW2, qW3);
    init_kenc<<<(BATCH * 80 * TK + 255) / 256, 256>>>(kb2);

    // 1) keys conv1 + fused pointwise conv2 (3-stage cp.async, 400 CTAs)
    cudaFuncSetAttribute(conv1_fused, cudaFuncAttributeMaxDynamicSharedMemorySize, C1_SMEM);
    conv1_fused<<<dim3(BATCH * TK / 64, 1024 / 128), 256, C1_SMEM>>>(kcol, kW1bf, kb1, kW2bf, kenc);

    // 2) fused query path (512 threads)
    cudaFuncSetAttribute(fused_q, cudaFuncAttributeMaxDynamicSharedMemorySize, QF_SMEM);
    fused_q<<<BATCH * TQ / 128, 512, QF_SMEM>>>(qbf, qW1bf, qb1, qW2bf, qb2, qW3bf, qb3, qenc);

    // 3) fused attention
    const int smem = (80 * TK + 32 * 81 + TK) * (int)sizeof(float);
    cudaFuncSetAttribute(attn_kernel, cudaFuncAttributeMaxDynamicSharedMemorySize, smem);
    attn_kernel<<<dim3(TQ / 32, BATCH), 256, smem>>>(qenc, kenc, prior, mask, attn_out, logp_out);
}

// round 8
// speedup vs baseline: 2.8213x; 1.0084x over previous
#include <cuda_runtime.h>
#include <cuda_bf16.h>
#include <math_constants.h>
#include <cstdint>
#include <cstddef>

#define BATCH 16
#define TQ 800
#define TK 200

// ---------------------------------------------------------------------------
// Device-global scratch (no allocations allowed)
// ---------------------------------------------------------------------------
__device__ __align__(16) __nv_bfloat16 g_kcol [BATCH * TK * 1536];   // im2col(keys)
__device__ __align__(16) __nv_bfloat16 g_qbf  [BATCH * 80  * TQ];
__device__ __align__(16) __nv_bfloat16 g_kW1bf[1024 * 1536];
__device__ __align__(16) __nv_bfloat16 g_kW2bf[80 * 1024];
__device__ __align__(16) __nv_bfloat16 g_qW1bf[160 * 240];
__device__ __align__(16) __nv_bfloat16 g_qW2bf[80 * 160];
__device__ __align__(16) __nv_bfloat16 g_qW3bf[80 * 80];
__device__ float g_kenc[BATCH * 80 * TK];
__device__ float g_qenc[BATCH * 80 * TQ];

__device__ __forceinline__ uint32_t smem_to_u32(const void* p) {
    uint32_t a;
    asm("{ .reg .u64 t; cvta.to.shared.u64 t, %1; cvt.u32.u64 %0, t; }" : "=r"(a) : "l"(p));
    return a;
}
__device__ __forceinline__ void ldsm_x4(uint32_t& r0, uint32_t& r1, uint32_t& r2, uint32_t& r3,
                                        uint32_t addr) {
    asm volatile("ldmatrix.sync.aligned.m8n8.x4.shared.b16 {%0,%1,%2,%3}, [%4];"
                 : "=r"(r0), "=r"(r1), "=r"(r2), "=r"(r3) : "r"(addr));
}
__device__ __forceinline__ void mma_bf16(float* c, uint32_t a0, uint32_t a1, uint32_t a2, uint32_t a3,
                                         uint32_t b0, uint32_t b1) {
    asm volatile("mma.sync.aligned.m16n8k16.row.col.f32.bf16.bf16.f32 "
                 "{%0,%1,%2,%3}, {%4,%5,%6,%7}, {%8,%9}, {%0,%1,%2,%3};"
                 : "+f"(c[0]), "+f"(c[1]), "+f"(c[2]), "+f"(c[3])
                 : "r"(a0), "r"(a1), "r"(a2), "r"(a3), "r"(b0), "r"(b1));
}
__device__ __forceinline__ void cp16(uint32_t dst, const void* src) {
    asm volatile("cp.async.ca.shared.global [%0], [%1], 16;" :: "r"(dst), "l"(src));
}
__device__ __forceinline__ void cp_commit() {
    asm volatile("cp.async.commit_group;" ::: "memory");
}

// ===========================================================================
// im2col(keys) f32 -> bf16: g_kcol[n=b*TK+t][k=ci*3+w]
// ===========================================================================
__global__ __launch_bounds__(256)
void im2col_keys(const float* __restrict__ keys)
{
    const int e = blockIdx.x * 256 + threadIdx.x;    // 3200 * 192
    if (e >= BATCH * TK * 192) return;
    const int n  = e / 192;
    const int kc = (e - n * 192) * 8;
    const int b  = n / TK;
    const int t  = n - b * TK;
    __nv_bfloat16 v[8];
    #pragma unroll
    for (int i = 0; i < 8; i++) {
        const int k  = kc + i;
        const int ci = k / 3;
        const int w  = k - ci * 3;
        const int tg = t + w - 1;
        v[i] = (tg >= 0 && tg < TK) ? __float2bfloat16(keys[((size_t)b * 512 + ci) * TK + tg])
                                    : __float2bfloat16(0.f);
    }
    *reinterpret_cast<uint4*>(&g_kcol[(size_t)n * 1536 + kc]) = *reinterpret_cast<uint4*>(v);
}

// ===========================================================================
// Keys-path weight conversion: kW1, kW2 (stream 0 chain)
// ===========================================================================
#define CK_S2 (1024 * 1536)
#define CK_S3 (80 * 1024)
#define CK_TOT (CK_S2 + CK_S3)

__global__ __launch_bounds__(256)
void convert_k(const float* __restrict__ kW1, const float* __restrict__ kW2)
{
    const long e = ((long)blockIdx.x * 256 + threadIdx.x) * 4;
    if (e >= CK_TOT) return;
    const float* src; __nv_bfloat16* dst; long off;
    if (e < CK_S2) { src = kW1; dst = g_kW1bf; off = e; }
    else           { src = kW2; dst = g_kW2bf; off = e - CK_S2; }
    const float4 v = *reinterpret_cast<const float4*>(src + off);
    __nv_bfloat162* d2 = reinterpret_cast<__nv_bfloat162*>(dst + off);
    d2[0] = __float22bfloat162_rn(make_float2(v.x, v.y));
    d2[1] = __float22bfloat162_rn(make_float2(v.z, v.w));
}

// ===========================================================================
// Query-path conversion: queries, qW1, qW2, qW3 (stream B chain)
// ===========================================================================
#define CQ_S1 (BATCH * 80 * TQ)
#define CQ_S4 (160 * 240)
#define CQ_S5 (80 * 160)
#define CQ_S6 (80 * 80)
#define CQ_O4 (CQ_S1)
#define CQ_O5 (CQ_O4 + CQ_S4)
#define CQ_O6 (CQ_O5 + CQ_S5)
#define CQ_TOT (CQ_O6 + CQ_S6)

__global__ __launch_bounds__(256)
void convert_q(const float* __restrict__ queries, const float* __restrict__ qW1,
               const float* __restrict__ qW2, const float* __restrict__ qW3)
{
    const long e = ((long)blockIdx.x * 256 + threadIdx.x) * 4;
    if (e >= CQ_TOT) return;
    const float* src; __nv_bfloat16* dst; long off;
    if      (e < CQ_O4) { src = queries; dst = g_qbf;   off = e; }
    else if (e < CQ_O5) { src = qW1;     dst = g_qW1bf; off = e - CQ_O4; }
    else if (e < CQ_O6) { src = qW2;     dst = g_qW2bf; off = e - CQ_O5; }
    else                { src = qW3;     dst = g_qW3bf; off = e - CQ_O6; }
    const float4 v = *reinterpret_cast<const float4*>(src + off);
    __nv_bfloat162* d2 = reinterpret_cast<__nv_bfloat162*>(dst + off);
    d2[0] = __float22bfloat162_rn(make_float2(v.x, v.y));
    d2[1] = __float22bfloat162_rn(make_float2(v.z, v.w));
}

__global__ __launch_bounds__(256)
void init_kenc(const float* __restrict__ kb2)
{
    const int idx = blockIdx.x * 256 + threadIdx.x;
    if (idx < BATCH * 80 * TK)
        g_kenc[idx] = kb2[(idx / TK) % 80];
}

// ===========================================================================
// keys conv1 (512->1024,k3) + fused pointwise conv2 (1024->80) via split-K.
// Tile 128m x 64n, grid 400. 3-stage cp.async. (unchanged from round 7)
// ===========================================================================
#define C1_K   1536
#define C1_LD  72
#define C2_LD  136
#define C1_SMEM 82944

__global__ __launch_bounds__(256)
void conv1_fused(const __nv_bfloat16* __restrict__ kcol, const __nv_bfloat16* __restrict__ W1,
                 const float* __restrict__ bias1, const __nv_bfloat16* __restrict__ W2,
                 float* __restrict__ kenc)
{
    extern __shared__ char dsm[];
    const uint32_t smb = smem_to_u32(dsm);
    const int tid  = threadIdx.x;
    const int wid  = tid >> 5;
    const int lane = tid & 31;
    const int m0 = blockIdx.y * 128;
    const int n0 = blockIdx.x * 64;
    const int warp_m = wid >> 1;
    const int warp_n = wid & 1;

    auto prefetch = [&](int ch, int st) {
        const int k0 = ch * 64;
        const uint32_t Ab = smb + st * 18432;
        const uint32_t Bb = smb + 55296 + st * 9216;
        #pragma unroll
        for (int j = 0; j < 4; j++) {
            const int e  = tid + 256 * j;
            const int r  = e >> 3;
            const int kq = (e & 7) << 3;
            cp16(Ab + (r * C1_LD + kq) * 2, W1 + (size_t)(m0 + r) * C1_K + k0 + kq);
        }
        #pragma unroll
        for (int j = 0; j < 2; j++) {
            const int e  = tid + 256 * j;
            const int r  = e >> 3;
            const int kq = (e & 7) << 3;
            cp16(Bb + (r * C1_LD + kq) * 2, kcol + (size_t)(n0 + r) * C1_K + k0 + kq);
        }
        cp_commit();
    };

    float acc[2][4][4];
    #pragma unroll
    for (int mt = 0; mt < 2; mt++)
        #pragma unroll
        for (int nt = 0; nt < 4; nt++)
            #pragma unroll
            for (int i = 0; i < 4; i++) acc[mt][nt][i] = 0.f;

    prefetch(0, 0);
    prefetch(1, 1);

    const uint32_t a_lane = ((warp_m * 32 + (lane & 15)) * C1_LD + (lane >> 4) * 8) * 2;
    const uint32_t b_lane = ((warp_n * 32 + (lane & 15)) * C1_LD + (lane >> 4) * 8) * 2;

    for (int ch = 0; ch < 24; ch++) {
        if (ch < 23) asm volatile("cp.async.wait_group 1;" ::: "memory");
        else         asm volatile("cp.async.wait_group 0;" ::: "memory");
        __syncthreads();

        const int st = ch % 3;
        const uint32_t a_addr0 = smb + st * 18432 + a_lane;
        const uint32_t b_addr0 = smb + 55296 + st * 9216 + b_lane;

        #pragma unroll
        for (int ks = 0; ks < 4; ks++) {
            const uint32_t koff = ks * 32;
            uint32_t a[2][4], b[2][4];
            #pragma unroll
            for (int mt = 0; mt < 2; mt++)
                ldsm_x4(a[mt][0], a[mt][1], a[mt][2], a[mt][3],
                        a_addr0 + mt * 16 * C1_LD * 2 + koff);
            #pragma unroll
            for (int np = 0; np < 2; np++)
                ldsm_x4(b[np][0], b[np][1], b[np][2], b[np][3],
                        b_addr0 + np * 16 * C1_LD * 2 + koff);
            #pragma unroll
            for (int mt = 0; mt < 2; mt++)
                #pragma unroll
                for (int np = 0; np < 2; np++) {
                    mma_bf16(acc[mt][np * 2 + 0], a[mt][0], a[mt][1], a[mt][2], a[mt][3],
                             b[np][0], b[np][2]);
                    mma_bf16(acc[mt][np * 2 + 1], a[mt][0], a[mt][1], a[mt][2], a[mt][3],
                             b[np][1], b[np][3]);
                }
        }
        if (ch + 2 < 24) prefetch(ch + 2, (ch + 2) % 3);
    }
    __syncthreads();

    __nv_bfloat16* Sh  = reinterpret_cast<__nv_bfloat16*>(dsm);            // 64n x 136
    __nv_bfloat16* W2s = reinterpret_cast<__nv_bfloat16*>(dsm + 17408);    // 80 x 136

    #pragma unroll
    for (int mt = 0; mt < 2; mt++) {
        const int col = warp_m * 32 + mt * 16 + (lane >> 2);
        const float bv0 = bias1[m0 + col];
        const float bv1 = bias1[m0 + col + 8];
        #pragma unroll
        for (int nt = 0; nt < 4; nt++) {
            const int nb = warp_n * 32 + (nt >> 1) * 16 + (nt & 1) * 8 + ((lane & 3) << 1);
            #pragma unroll
            for (int cc = 0; cc < 2; cc++) {
                Sh[(nb + cc) * C2_LD + col]     = __float2bfloat16(fmaxf(acc[mt][nt][cc]     + bv0, 0.f));
                Sh[(nb + cc) * C2_LD + col + 8] = __float2bfloat16(fmaxf(acc[mt][nt][2 + cc] + bv1, 0.f));
            }
        }
    }
    for (int e = tid; e < 80 * 32; e += 256) {
        const int r = e >> 5;
        const int q = (e & 31) << 2;
        *reinterpret_cast<uint2*>(&W2s[r * C2_LD + q]) =
            *reinterpret_cast<const uint2*>(W2 + (size_t)r * 1024 + m0 + q);
    }
    __syncthreads();

    if (wid < 4) {
        const uint32_t sh_addr = smem_to_u32(Sh)  + ((wid * 16 + (lane & 15)) * C2_LD + (lane >> 4) * 8) * 2;
        const uint32_t w2_addr = smem_to_u32(W2s) + ((lane & 15) * C2_LD + (lane >> 4) * 8) * 2;
        float acc2[5][2][4];
        #pragma unroll
        for (int ct = 0; ct < 5; ct++)
            #pragma unroll
            for (int s = 0; s < 2; s++)
                #pragma unroll
                for (int i = 0; i < 4; i++) acc2[ct][s][i] = 0.f;

        #pragma unroll
        for (int ks = 0; ks < 8; ks++) {
            const uint32_t koff = ks * 32;
            uint32_t a0, a1, a2, a3;
            ldsm_x4(a0, a1, a2, a3, sh_addr + koff);
            #pragma unroll
            for (int ct = 0; ct < 5; ct++) {
                uint32_t b0, b1, b2, b3;
                ldsm_x4(b0, b1, b2, b3, w2_addr + ct * 16 * C2_LD * 2 + koff);
                mma_bf16(acc2[ct][0], a0, a1, a2, a3, b0, b2);
                mma_bf16(acc2[ct][1], a0, a1, a2, a3, b1, b3);
            }
        }
        #pragma unroll
        for (int ct = 0; ct < 5; ct++)
            #pragma unroll
            for (int s = 0; s < 2; s++)
                #pragma unroll
                for (int i = 0; i < 4; i++) {
                    const int co2 = ct * 16 + s * 8 + ((lane & 3) << 1) + (i & 1);
                    const int n   = n0 + wid * 16 + (lane >> 2) + ((i >> 1) << 3);
                    const int bb  = n / TK;
                    const int t   = n - bb * TK;
                    atomicAdd(kenc + ((size_t)bb * 80 + co2) * TK + t, acc2[ct][s][i]);
                }
    }
}

// ===========================================================================
// FUSED query path, 512 threads (unchanged).
// ===========================================================================
#define QF_SMEM 185856

__global__ __launch_bounds__(512)
void fused_q(const __nv_bfloat16* __restrict__ qbf,
             const __nv_bfloat16* __restrict__ W1, const float* __restrict__ b1,
             const __nv_bfloat16* __restrict__ W2, const float* __restrict__ b2,
             const __nv_bfloat16* __restrict__ W3, const float* __restrict__ b3,
             float* __restrict__ qenc)
{
    extern __shared__ char dsm[];
    __nv_bfloat16* A1  = reinterpret_cast<__nv_bfloat16*>(dsm);
    __nv_bfloat16* W1s = reinterpret_cast<__nv_bfloat16*>(dsm + 63488);
    __nv_bfloat16* H1  = reinterpret_cast<__nv_bfloat16*>(dsm + 142848);
    __nv_bfloat16* W2s = reinterpret_cast<__nv_bfloat16*>(dsm);
    __nv_bfloat16* H2  = reinterpret_cast<__nv_bfloat16*>(dsm + 26880);
    __nv_bfloat16* W3s = reinterpret_cast<__nv_bfloat16*>(dsm + 49408);

    const int tid  = threadIdx.x;
    const int wid  = tid >> 5;
    const int lane = tid & 31;
    const int n0   = blockIdx.x * 128;
    const int rowq = (lane & 15);
    const int kq8  = (lane >> 4) * 8;

    #pragma unroll
    for (int j = 0; j < 15; j++) {
        const int kl = (tid >> 5) + j * 16;
        const int ci = kl / 3;
        const int w  = kl - ci * 3;
        #pragma unroll
        for (int i = 0; i < 4; i++) {
            const int r  = ((tid & 31) << 2) + i;
            const int n  = n0 + r;
            const int bb = n / TQ;
            const int t  = n - bb * TQ;
            const int tg = t + w - 1;
            __nv_bfloat16 v = __float2bfloat16(0.f);
            if (tg >= 0 && tg < TQ) v = qbf[((size_t)bb * 80 + ci) * TQ + tg];
            A1[r * 248 + kl] = v;
        }
    }
    for (int e = tid; e < 160 * 60; e += 512) {
        const int r = e / 60;
        const int q = (e - r * 60) * 4;
        *reinterpret_cast<uint2*>(&W1s[r * 248 + q]) =
            *reinterpret_cast<const uint2*>(W1 + (size_t)r * 240 + q);
    }
    __syncthreads();

    {
        const int ng  = wid & 7;
        const int coh = (wid >> 3) * 80;
        const uint32_t a_addr = smem_to_u32(A1)  + ((ng * 16 + rowq) * 248 + kq8) * 2;
        const uint32_t b_addr = smem_to_u32(W1s) + ((coh + rowq) * 248 + kq8) * 2;
        float acc1[5][2][4];
        #pragma unroll
        for (int ct = 0; ct < 5; ct++)
            #pragma unroll
            for (int s = 0; s < 2; s++)
                #pragma unroll
                for (int i = 0; i < 4; i++) acc1[ct][s][i] = 0.f;
        #pragma unroll
        for (int ks = 0; ks < 15; ks++) {
            const uint32_t koff = ks * 32;
            uint32_t a0, a1, a2, a3;
            ldsm_x4(a0, a1, a2, a3, a_addr + koff);
            #pragma unroll
            for (int ct = 0; ct < 5; ct++) {
                uint32_t b0, b1, b2, b3;
                ldsm_x4(b0, b1, b2, b3, b_addr + ct * 16 * 248 * 2 + koff);
                mma_bf16(acc1[ct][0], a0, a1, a2, a3, b0, b2);
                mma_bf16(acc1[ct][1], a0, a1, a2, a3, b1, b3);
            }
        }
        __syncthreads();
        #pragma unroll
        for (int ct = 0; ct < 5; ct++)
            #pragma unroll
            for (int s = 0; s < 2; s++)
                #pragma unroll
                for (int i = 0; i < 4; i++) {
                    const int co = coh + ct * 16 + s * 8 + ((lane & 3) << 1) + (i & 1);
                    const int nl = ng * 16 + (lane >> 2) + ((i >> 1) << 3);
                    H1[nl * 168 + co] = __float2bfloat16(fmaxf(acc1[ct][s][i] + b1[co], 0.f));
                }
    }
    for (int e = tid; e < 80 * 40; e += 512) {
        const int r = e / 40;
        const int q = (e - r * 40) * 4;
        *reinterpret_cast<uint2*>(&W2s[r * 168 + q]) =
            *reinterpret_cast<const uint2*>(W2 + (size_t)r * 160 + q);
    }
    __syncthreads();

    if (wid >= 8) {
        for (int e = tid - 256; e < 80 * 20; e += 256) {
            const int r = e / 20;
            const int q = (e - r * 20) * 4;
            *reinterpret_cast<uint2*>(&W3s[r * 88 + q]) =
                *reinterpret_cast<const uint2*>(W3 + (size_t)r * 80 + q);
        }
    } else {
        const uint32_t a_addr = smem_to_u32(H1)  + ((wid * 16 + rowq) * 168 + kq8) * 2;
        const uint32_t b_addr = smem_to_u32(W2s) + (rowq * 168 + kq8) * 2;
        float acc2[5][2][4];
        #pragma unroll
        for (int ct = 0; ct < 5; ct++)
            #pragma unroll
            for (int s = 0; s < 2; s++)
                #pragma unroll
                for (int i = 0; i < 4; i++) acc2[ct][s][i] = 0.f;
        #pragma unroll
        for (int ks = 0; ks < 10; ks++) {
            const uint32_t koff = ks * 32;
            uint32_t a0, a1, a2, a3;
            ldsm_x4(a0, a1, a2, a3, a_addr + koff);
            #pragma unroll
            for (int ct = 0; ct < 5; ct++) {
                uint32_t b0, b1, b2, b3;
                ldsm_x4(b0, b1, b2, b3, b_addr + ct * 16 * 168 * 2 + koff);
                mma_bf16(acc2[ct][0], a0, a1, a2, a3, b0, b2);
                mma_bf16(acc2[ct][1], a0, a1, a2, a3, b1, b3);
            }
        }
        #pragma unroll
        for (int ct = 0; ct < 5; ct++)
            #pragma unroll
            for (int s = 0; s < 2; s++)
                #pragma unroll
                for (int i = 0; i < 4; i++) {
                    const int co = ct * 16 + s * 8 + ((lane & 3) << 1) + (i & 1);
                    const int nl = wid * 16 + (lane >> 2) + ((i >> 1) << 3);
                    H2[nl * 88 + co] = __float2bfloat16(fmaxf(acc2[ct][s][i] + b2[co], 0.f));
                }
    }
    __syncthreads();

    if (wid < 8) {
        const uint32_t a_addr = smem_to_u32(H2)  + ((wid * 16 + rowq) * 88 + kq8) * 2;
        const uint32_t b_addr = smem_to_u32(W3s) + (rowq * 88 + kq8) * 2;
        float acc3[5][2][4];
        #pragma unroll
        for (int ct = 0; ct < 5; ct++)
            #pragma unroll
            for (int s = 0; s < 2; s++)
                #pragma unroll
                for (int i = 0; i < 4; i++) acc3[ct][s][i] = 0.f;
        #pragma unroll
        for (int ks = 0; ks < 5; ks++) {
            const uint32_t koff = ks * 32;
            uint32_t a0, a1, a2, a3;
            ldsm_x4(a0, a1, a2, a3, a_addr + koff);
            #pragma unroll
            for (int ct = 0; ct < 5; ct++) {
                uint32_t b0, b1, b2, b3;
                ldsm_x4(b0, b1, b2, b3, b_addr + ct * 16 * 88 * 2 + koff);
                mma_bf16(acc3[ct][0], a0, a1, a2, a3, b0, b2);
                mma_bf16(acc3[ct][1], a0, a1, a2, a3, b1, b3);
            }
        }
        #pragma unroll
        for (int ct = 0; ct < 5; ct++)
            #pragma unroll
            for (int s = 0; s < 2; s++)
                #pragma unroll
                for (int i = 0; i < 4; i++) {
                    const int co = ct * 16 + s * 8 + ((lane & 3) << 1) + (i & 1);
                    const int n  = n0 + wid * 16 + (lane >> 2) + ((i >> 1) << 3);
                    const int bb = n / TQ;
                    const int t  = n - bb * TQ;
                    qenc[((size_t)bb * 80 + co) * TQ + t] = acc3[ct][s][i] + b3[co];
                }
    }
}

// ---------------------------------------------------------------------------
// Fused attention (unchanged)
// ---------------------------------------------------------------------------
static __device__ __forceinline__ float warp_max(float v) {
    #pragma unroll
    for (int o = 16; o > 0; o >>= 1) v = fmaxf(v, __shfl_xor_sync(0xffffffffu, v, o));
    return v;
}
static __device__ __forceinline__ float warp_sum(float v) {
    #pragma unroll
    for (int o = 16; o > 0; o >>= 1) v += __shfl_xor_sync(0xffffffffu, v, o);
    return v;
}

__global__ __launch_bounds__(256)
void attn_kernel(const float* __restrict__ qenc, const float* __restrict__ kenc,
                 const float* __restrict__ prior, const unsigned char* __restrict__ mask,
                 float* __restrict__ attn_out, float* __restrict__ logp_out)
{
    extern __shared__ float sm[];
    float* Ks  = sm;
    float* Qs  = sm + 80 * TK;
    float* k2s = Qs + 32 * 81;

    const int b   = blockIdx.y;
    const int q0  = blockIdx.x * 32;
    const int tid = threadIdx.x;

    const float* kb = kenc + (size_t)b * 80 * TK;
    for (int i = tid; i < 80 * TK / 4; i += 256)
        reinterpret_cast<float4*>(Ks)[i] = reinterpret_cast<const float4*>(kb)[i];

    const float* qb = qenc + (size_t)b * 80 * TQ;
    {
        const int ql = tid & 31;
        for (int c = tid >> 5; c < 80; c += 8)
            Qs[ql * 81 + c] = qb[c * TQ + q0 + ql];
    }
    __syncthreads();

    for (int k = tid; k < TK; k += 256) {
        float s = 0.f;
        #pragma unroll 8
        for (int c = 0; c < 80; c++) { const float v = Ks[c * TK + k]; s = fmaf(v, v, s); }
        k2s[k] = s;
    }
    __syncthreads();

    const int warp = tid >> 5, lane = tid & 31;
    constexpr int KI = 7;

    float s[4][KI];
    #pragma unroll
    for (int r = 0; r < 4; r++)
        #pragma unroll
        for (int i = 0; i < KI; i++) s[r][i] = 0.f;

    for (int c = 0; c < 80; c++) {
        float qv[4];
        #pragma unroll
        for (int r = 0; r < 4; r++) qv[r] = Qs[(warp * 4 + r) * 81 + c];
        float kv[KI];
        #pragma unroll
        for (int i = 0; i < 6; i++) kv[i] = Ks[c * TK + lane + 32 * i];
        kv[6] = (lane < 8) ? Ks[c * TK + lane + 192] : 0.f;
        #pragma unroll
        for (int r = 0; r < 4; r++)
            #pragma unroll
            for (int i = 0; i < KI; i++)
                s[r][i] = fmaf(qv[r], kv[i], s[r][i]);
    }

    const float NEG_INF = -CUDART_INF_F;
    #pragma unroll
    for (int r = 0; r < 4; r++) {
        const int q = q0 + warp * 4 + r;
        const size_t row = ((size_t)b * TQ + q) * TK;

        float m1 = NEG_INF;
        #pragma unroll
        for (int i = 0; i < KI; i++) {
            const int k = lane + 32 * i;
            const float sc = (k < TK) ? -5e-4f * (k2s[k] - 2.f * s[r][i]) : NEG_INF;
            s[r][i] = sc;
            m1 = fmaxf(m1, sc);
        }
        m1 = warp_max(m1);

        float e[KI];
        float se = 0.f;
        #pragma unroll
        for (int i = 0; i < KI; i++) {
            const int k = lane + 32 * i;
            if (k < TK) { e[i] = __expf(s[r][i] - m1); se += e[i]; }
        }
        se = warp_sum(se);
        const float lse = m1 + __logf(se);

        float se2 = 0.f;
        #pragma unroll
        for (int i = 0; i < KI; i++) {
            const int k = lane + 32 * i;
            if (k < TK) {
                const float pr = prior[row + k] + 1e-8f;
                logp_out[row + k] = s[r][i] - lse + __logf(pr);
                const float wv = mask[b * TK + k] ? 0.f : e[i] * pr;
                e[i] = wv;
                se2 += wv;
            }
        }
        se2 = warp_sum(se2);
        const float inv = 1.f / se2;
        #pragma unroll
        for (int i = 0; i < KI; i++) {
            const int k = lane + 32 * i;
            if (k < TK) attn_out[row + k] = e[i] * inv;
        }
    }
}

// ---------------------------------------------------------------------------
extern "C" void kernel_launch(void* const* d_in, const int* in_sizes, int n_in,
                              void* d_out, int out_size)
{
    const float* queries = (const float*)d_in[0];
    const float* keys    = (const float*)d_in[1];
    const unsigned char* mask = (const unsigned char*)d_in[3];
    const float* prior   = (const float*)d_in[4];
    const float* kW1 = (const float*)d_in[5];
    const float* kb1 = (const float*)d_in[6];
    const float* kW2 = (const float*)d_in[7];
    const float* kb2 = (const float*)d_in[8];
    const float* qW1 = (const float*)d_in[9];
    const float* qb1 = (const float*)d_in[10];
    const float* qW2 = (const float*)d_in[11];
    const float* qb2 = (const float*)d_in[12];
    const float* qW3 = (const float*)d_in[13];
    const float* qb3 = (const float*)d_in[14];

    float* out      = (float*)d_out;
    float* attn_out = out;
    float* logp_out = out + (size_t)BATCH * TQ * TK;

    __nv_bfloat16 *kcol, *qbf, *kW1bf, *kW2bf, *qW1bf, *qW2bf, *qW3bf;
    float *kenc, *qenc;
    cudaGetSymbolAddress((void**)&kcol,  g_kcol);
    cudaGetSymbolAddress((void**)&qbf,   g_qbf);
    cudaGetSymbolAddress((void**)&kW1bf, g_kW1bf);
    cudaGetSymbolAddress((void**)&kW2bf, g_kW2bf);
    cudaGetSymbolAddress((void**)&qW1bf, g_qW1bf);
    cudaGetSymbolAddress((void**)&qW2bf, g_qW2bf);
    cudaGetSymbolAddress((void**)&qW3bf, g_qW3bf);
    cudaGetSymbolAddress((void**)&kenc,  g_kenc);
    cudaGetSymbolAddress((void**)&qenc,  g_qenc);

    // One-time creation of the side stream + fork/join events (reused across
    // calls; identical recorded work every call, so graph capture stays
    // deterministic).
    static cudaStream_t sB = nullptr;
    static cudaEvent_t evFork = nullptr, evJoin = nullptr;
    if (sB == nullptr) {
        cudaStreamCreateWithFlags(&sB, cudaStreamNonBlocking);
        cudaEventCreateWithFlags(&evFork, cudaEventDisableTiming);
        cudaEventCreateWithFlags(&evJoin, cudaEventDisableTiming);
        cudaFuncSetAttribute(conv1_fused, cudaFuncAttributeMaxDynamicSharedMemorySize, C1_SMEM);
        cudaFuncSetAttribute(fused_q,     cudaFuncAttributeMaxDynamicSharedMemorySize, QF_SMEM);
        cudaFuncSetAttribute(attn_kernel, cudaFuncAttributeMaxDynamicSharedMemorySize,
                             (80 * TK + 32 * 81 + TK) * (int)sizeof(float));
    }

    // ---- fork: stream B runs the independent query path ----
    cudaEventRecord(evFork, 0);
    cudaStreamWaitEvent(sB, evFork, 0);

    convert_q<<<(CQ_TOT / 4 + 255) / 256, 256, 0, sB>>>(queries, qW1, qW2, qW3);
    fused_q<<<BATCH * TQ / 128, 512, QF_SMEM, sB>>>(qbf, qW1bf, qb1, qW2bf, qb2, qW3bf, qb3, qenc);
    cudaEventRecord(evJoin, sB);

    // ---- stream 0: keys path ----
    im2col_keys<<<(BATCH * TK * 192 + 255) / 256, 256>>>(keys);
    convert_k<<<(CK_TOT / 4 + 255) / 256, 256>>>(kW1, kW2);
    init_kenc<<<(BATCH * 80 * TK + 255) / 256, 256>>>(kb2);
    conv1_fused<<<dim3(BATCH * TK / 64, 1024 / 128), 256, C1_SMEM>>>(kcol, kW1bf, kb1, kW2bf, kenc);

    // ---- join, then attention ----
    cudaStreamWaitEvent(0, evJoin, 0);
    const int smem = (80 * TK + 32 * 81 + TK) * (int)sizeof(float);
    attn_kernel<<<dim3(TQ / 32, BATCH), 256, smem>>>(qenc, kenc, prior, mask, attn_out, logp_out);
}